// round 4
// baseline (speedup 1.0000x reference)
#include <cuda_runtime.h>
#include <math.h>

#define NN 65536
#define GG 1024
#define SSZ 64
#define DD 64
#define OBSD 256
#define HIDD 512

// ---------------- scratch (device globals; no allocations allowed) ----------
__device__ float g_inter_emb[NN * DD];          // 16 MB
__device__ float g_intra_emb[NN * DD];          // 16 MB
__device__ float g_pooled[GG * DD];
__device__ float g_qkv[2][GG * 3 * DD];         // inter qkv, mu/std
__device__ float g_attno[2][GG * DD];           // inter attention output
__device__ float g_inter_mu[GG * DD];
__device__ float g_inter_std[GG * DD];
__device__ float g_inter_sample[GG * DD];

__device__ __forceinline__ float softplusf(float x) {
    return (x > 20.f) ? x : log1pf(expf(x));
}

// ---------------------------------------------------------------------------
// K1: fused embedding GEMM  C = tanh(obs @ W^T + b)
// grid (512, 10): y<8 -> local_obs (512 cols) into after_comm[:,0:512]
//                 y==8 -> inter_emb, y==9 -> intra_emb
// Tile 128x64x32, 256 threads, 8x4 register blocking.
// ---------------------------------------------------------------------------
__global__ __launch_bounds__(256) void k1_embed(
    const float* __restrict__ A,
    const float* __restrict__ lw, const float* __restrict__ lb,
    const float* __restrict__ iw, const float* __restrict__ ib,
    const float* __restrict__ tw, const float* __restrict__ tb,
    float* __restrict__ out_ac)
{
    __shared__ float As[32][132];
    __shared__ float Bs[32][68];

    int t = threadIdx.x;
    int row0 = blockIdx.x * 128;
    int by = blockIdx.y;

    const float* W; const float* bias; int cb;
    if (by < 8)      { W = lw; bias = lb; cb = by * 64; }
    else if (by == 8){ W = iw; bias = ib; cb = 0; }
    else             { W = tw; bias = tb; cb = 0; }

    int ty = t >> 4, tx = t & 15;
    float acc[8][4];
    #pragma unroll
    for (int i = 0; i < 8; i++)
        #pragma unroll
        for (int j = 0; j < 4; j++) acc[i][j] = 0.f;

    int ar  = t >> 1;          // A tile row
    int akv = (t & 1) * 4;     // A float4 group base
    int bj  = t & 63;          // W tile row
    int bkv = t >> 6;          // 0..3

    for (int kt = 0; kt < 8; kt++) {
        int k0 = kt * 32;
        #pragma unroll
        for (int i = 0; i < 4; i++) {
            float4 v = *(const float4*)&A[(size_t)(row0 + ar) * OBSD + k0 + (akv + i) * 4];
            As[(akv + i) * 4 + 0][ar] = v.x;
            As[(akv + i) * 4 + 1][ar] = v.y;
            As[(akv + i) * 4 + 2][ar] = v.z;
            As[(akv + i) * 4 + 3][ar] = v.w;
        }
        #pragma unroll
        for (int i = 0; i < 2; i++) {
            float4 v = *(const float4*)&W[(size_t)(cb + bj) * OBSD + k0 + bkv * 8 + i * 4];
            Bs[bkv * 8 + i * 4 + 0][bj] = v.x;
            Bs[bkv * 8 + i * 4 + 1][bj] = v.y;
            Bs[bkv * 8 + i * 4 + 2][bj] = v.z;
            Bs[bkv * 8 + i * 4 + 3][bj] = v.w;
        }
        __syncthreads();
        #pragma unroll
        for (int k = 0; k < 32; k++) {
            float4 a0 = *(const float4*)&As[k][ty * 8];
            float4 a1 = *(const float4*)&As[k][ty * 8 + 4];
            float4 b  = *(const float4*)&Bs[k][tx * 4];
            float av[8] = {a0.x, a0.y, a0.z, a0.w, a1.x, a1.y, a1.z, a1.w};
            float bv[4] = {b.x, b.y, b.z, b.w};
            #pragma unroll
            for (int i = 0; i < 8; i++)
                #pragma unroll
                for (int j = 0; j < 4; j++)
                    acc[i][j] = fmaf(av[i], bv[j], acc[i][j]);
        }
        __syncthreads();
    }

    float bvv[4];
    #pragma unroll
    for (int j = 0; j < 4; j++) bvv[j] = bias[cb + tx * 4 + j];

    #pragma unroll
    for (int i = 0; i < 8; i++) {
        int row = row0 + ty * 8 + i;
        float4 o;
        o.x = tanhf(acc[i][0] + bvv[0]);
        o.y = tanhf(acc[i][1] + bvv[1]);
        o.z = tanhf(acc[i][2] + bvv[2]);
        o.w = tanhf(acc[i][3] + bvv[3]);
        if (by < 8)       *(float4*)&out_ac[(size_t)row * 640 + by * 64 + tx * 4] = o;
        else if (by == 8) *(float4*)&g_inter_emb[(size_t)row * 64 + tx * 4] = o;
        else              *(float4*)&g_intra_emb[(size_t)row * 64 + tx * 4] = o;
    }
}

// ---------------------------------------------------------------------------
// K3: softmax pooling per group. 1 block / group, 64 threads.
// ---------------------------------------------------------------------------
__global__ __launch_bounds__(64) void k3_pool(
    const int* __restrict__ sets,
    const float* __restrict__ aw, const float* __restrict__ ab)
{
    __shared__ float X[64][65];
    __shared__ float wgt[64];
    __shared__ int rows[64];
    __shared__ float wm[2], wsum[2];

    int t = threadIdx.x;
    int g = blockIdx.x;
    rows[t] = sets[g * 64 + t];
    __syncthreads();
    for (int l = 0; l < 64; l++)
        X[l][t] = g_inter_emb[(size_t)rows[l] * 64 + t];
    __syncthreads();

    float lg = ab[0];
    #pragma unroll 8
    for (int k = 0; k < 64; k++) lg = fmaf(X[t][k], aw[k], lg);

    float m = lg;
    #pragma unroll
    for (int o = 16; o; o >>= 1) m = fmaxf(m, __shfl_xor_sync(0xffffffffu, m, o));
    if ((t & 31) == 0) wm[t >> 5] = m;
    __syncthreads();
    m = fmaxf(wm[0], wm[1]);
    float e = expf(lg - m);
    float s = e;
    #pragma unroll
    for (int o = 16; o; o >>= 1) s += __shfl_xor_sync(0xffffffffu, s, o);
    if ((t & 31) == 0) wsum[t >> 5] = s;
    __syncthreads();
    s = wsum[0] + wsum[1];
    wgt[t] = e / s;
    __syncthreads();

    float acc = 0.f;
    #pragma unroll 8
    for (int k = 0; k < 64; k++) acc = fmaf(wgt[k], X[k][t], acc);
    g_pooled[g * 64 + t] = acc;
}

// ---------------------------------------------------------------------------
// K4a: inter QKV = pooled @ w_in^T + b.  grid (16, 2[mu/std]), 256 thr.
// ---------------------------------------------------------------------------
__global__ __launch_bounds__(256) void k4a_qkv(
    const float* __restrict__ wmi, const float* __restrict__ bmi,
    const float* __restrict__ wsi, const float* __restrict__ bsi)
{
    __shared__ float X[64][65];
    int t = threadIdx.x;
    int r0 = blockIdx.x * 64;
    int p = blockIdx.y;
    const float* Wi = p ? wsi : wmi;
    const float* bi = p ? bsi : bmi;

    {
        int l = t >> 2, c = (t & 3) * 16;
        #pragma unroll
        for (int i = 0; i < 4; i++) {
            float4 v = *(const float4*)&g_pooled[(r0 + l) * 64 + c + i * 4];
            X[l][c + i * 4 + 0] = v.x;
            X[l][c + i * 4 + 1] = v.y;
            X[l][c + i * 4 + 2] = v.z;
            X[l][c + i * 4 + 3] = v.w;
        }
    }
    __syncthreads();

    int l  = t & 63;
    int jb = t >> 6;
    for (int jj = 0; jj < 48; jj++) {
        int j = jb * 48 + jj;
        float acc = bi[j];
        #pragma unroll 8
        for (int k = 0; k < 64; k++) acc = fmaf(X[l][k], __ldg(&Wi[j * 64 + k]), acc);
        g_qkv[p][(r0 + l) * 192 + j] = acc;
    }
}

// ---------------------------------------------------------------------------
// K4b: inter attention (L=1024, dh=16). grid (16 qtiles, 4 heads, 2 passes),
// 64 threads, K/V head slice staged in 128 KB dynamic smem, online softmax.
// ---------------------------------------------------------------------------
__global__ __launch_bounds__(64) void k4b_attn()
{
    extern __shared__ float sm4b[];
    float* Ks = sm4b;
    float* Vs = sm4b + 1024 * 16;

    int t  = threadIdx.x;
    int q0 = blockIdx.x * 64;
    int h  = blockIdx.y;
    int p  = blockIdx.z;
    const float* QKV = g_qkv[p];

    for (int r = t; r < 1024; r += 64) {
        #pragma unroll
        for (int i = 0; i < 4; i++) {
            float4 kv = *(const float4*)&QKV[(size_t)r * 192 + 64 + h * 16 + i * 4];
            *(float4*)&Ks[r * 16 + i * 4] = kv;
            float4 vv = *(const float4*)&QKV[(size_t)r * 192 + 128 + h * 16 + i * 4];
            *(float4*)&Vs[r * 16 + i * 4] = vv;
        }
    }
    __syncthreads();

    float q[16];
    #pragma unroll
    for (int i = 0; i < 16; i++) q[i] = QKV[(size_t)(q0 + t) * 192 + h * 16 + i];

    float m = -1e30f, ssum = 0.f, acc[16];
    #pragma unroll
    for (int i = 0; i < 16; i++) acc[i] = 0.f;

    for (int j = 0; j < 1024; j++) {
        float s = 0.f;
        #pragma unroll
        for (int c = 0; c < 16; c++) s = fmaf(q[c], Ks[j * 16 + c], s);
        s *= 0.25f;
        float nm = fmaxf(m, s);
        float corr = expf(m - nm);
        float w = expf(s - nm);
        ssum = ssum * corr + w;
        #pragma unroll
        for (int c = 0; c < 16; c++) acc[c] = fmaf(acc[c], corr, w * Vs[j * 16 + c]);
        m = nm;
    }
    float inv = 1.f / ssum;
    #pragma unroll
    for (int c = 0; c < 16; c++)
        g_attno[p][(size_t)(q0 + t) * 64 + h * 16 + c] = acc[c] * inv;
}

// ---------------------------------------------------------------------------
// K4c: inter out-proj, softplus, sample. grid 16, 256 threads.
// ---------------------------------------------------------------------------
__global__ __launch_bounds__(256) void k4c_proj(
    const float* __restrict__ wmo, const float* __restrict__ bmo,
    const float* __restrict__ wso, const float* __restrict__ bso,
    const float* __restrict__ eps_inter)
{
    __shared__ float Om[64][65];
    __shared__ float Os[64][65];
    int t = threadIdx.x;
    int r0 = blockIdx.x * 64;
    {
        int l = t >> 2, c = (t & 3) * 16;
        for (int i = 0; i < 16; i++) {
            Om[l][c + i] = g_attno[0][(size_t)(r0 + l) * 64 + c + i];
            Os[l][c + i] = g_attno[1][(size_t)(r0 + l) * 64 + c + i];
        }
    }
    __syncthreads();

    int lb = t >> 4, db = t & 15;
    float am[4][4], as[4][4];
    #pragma unroll
    for (int i = 0; i < 4; i++)
        #pragma unroll
        for (int j = 0; j < 4; j++) { am[i][j] = 0.f; as[i][j] = 0.f; }

    #pragma unroll 4
    for (int k = 0; k < 64; k++) {
        float om[4], os[4], wmv[4], wsv[4];
        #pragma unroll
        for (int i = 0; i < 4; i++) { om[i] = Om[lb * 4 + i][k]; os[i] = Os[lb * 4 + i][k]; }
        #pragma unroll
        for (int j = 0; j < 4; j++) {
            wmv[j] = __ldg(&wmo[(db * 4 + j) * 64 + k]);
            wsv[j] = __ldg(&wso[(db * 4 + j) * 64 + k]);
        }
        #pragma unroll
        for (int i = 0; i < 4; i++)
            #pragma unroll
            for (int j = 0; j < 4; j++) {
                am[i][j] = fmaf(om[i], wmv[j], am[i][j]);
                as[i][j] = fmaf(os[i], wsv[j], as[i][j]);
            }
    }
    #pragma unroll
    for (int i = 0; i < 4; i++) {
        int gi = r0 + lb * 4 + i;
        #pragma unroll
        for (int j = 0; j < 4; j++) {
            int d = db * 4 + j;
            float mu  = am[i][j] + bmo[d];
            float st  = softplusf(as[i][j] + bso[d] - 5.f);
            g_inter_mu[gi * 64 + d] = mu;
            g_inter_std[gi * 64 + d] = st;
            g_inter_sample[gi * 64 + d] = fmaf(st, eps_inter[gi * 64 + d], mu);
        }
    }
}

// ---------------------------------------------------------------------------
// K2: intra MHA per group (mu then std), fused with ALL final scatter writes.
// 1 block / group, 256 threads, ~168 KB dynamic smem.
// ---------------------------------------------------------------------------
__global__ __launch_bounds__(256) void k2_intra(
    const int* __restrict__ sets,
    const float* __restrict__ wmi, const float* __restrict__ bmi,
    const float* __restrict__ wmo, const float* __restrict__ bmo,
    const float* __restrict__ wsi, const float* __restrict__ bsi,
    const float* __restrict__ wso, const float* __restrict__ bso,
    const float* __restrict__ eps_intra,
    float* __restrict__ out_ac, float* __restrict__ out_mu, float* __restrict__ out_std)
{
    extern __shared__ float sm[];
    float* X    = sm;                  // [64][65]
    float* Wi   = X + 64 * 65;         // [192][65]
    float* bin  = Wi + 192 * 65;       // [192]
    float* QKV  = bin + 192;           // [64][196]
    float* O    = QKV + 64 * 196;      // [64][65]
    float* Wo   = O + 64 * 65;         // [64][65]
    float* bout = Wo + 64 * 65;        // [64]
    float* MUb  = bout + 64;           // [64][64]
    int*   rows = (int*)(MUb + 64 * 64); // [64]

    int t = threadIdx.x;
    int g = blockIdx.x;
    if (t < 64) rows[t] = sets[g * 64 + t];
    __syncthreads();
    {
        int l = t >> 2, c = (t & 3) * 16;
        const float* src = &g_intra_emb[(size_t)rows[l] * 64 + c];
        #pragma unroll
        for (int i = 0; i < 4; i++) {
            float4 v = *(const float4*)&src[i * 4];
            X[l * 65 + c + i * 4 + 0] = v.x;
            X[l * 65 + c + i * 4 + 1] = v.y;
            X[l * 65 + c + i * 4 + 2] = v.z;
            X[l * 65 + c + i * 4 + 3] = v.w;
        }
    }

    for (int p = 0; p < 2; p++) {
        const float* wIn  = p ? wsi : wmi;
        const float* bIn  = p ? bsi : bmi;
        const float* wOut = p ? wso : wmo;
        const float* bOut = p ? bso : bmo;
        __syncthreads();
        // load weights
        for (int v = t; v < 3072; v += 256) {
            int j = v >> 4; int cv = (v & 15) * 4;
            float4 w4 = *(const float4*)&wIn[j * 64 + cv];
            Wi[j * 65 + cv + 0] = w4.x; Wi[j * 65 + cv + 1] = w4.y;
            Wi[j * 65 + cv + 2] = w4.z; Wi[j * 65 + cv + 3] = w4.w;
        }
        if (t < 192) bin[t] = bIn[t];
        for (int v = t; v < 1024; v += 256) {
            int j = v >> 4; int cv = (v & 15) * 4;
            float4 w4 = *(const float4*)&wOut[j * 64 + cv];
            Wo[j * 65 + cv + 0] = w4.x; Wo[j * 65 + cv + 1] = w4.y;
            Wo[j * 65 + cv + 2] = w4.z; Wo[j * 65 + cv + 3] = w4.w;
        }
        if (t < 64) bout[t] = bOut[t];
        __syncthreads();

        // QKV = X @ Wi^T + b  (thread: 4 rows x 12 cols)
        {
            int lb = t >> 4, jb = t & 15;
            float acc[4][12];
            #pragma unroll
            for (int i = 0; i < 4; i++)
                #pragma unroll
                for (int j = 0; j < 12; j++) acc[i][j] = 0.f;
            #pragma unroll 4
            for (int k = 0; k < 64; k++) {
                float xv[4], wv[12];
                #pragma unroll
                for (int i = 0; i < 4; i++) xv[i] = X[(lb * 4 + i) * 65 + k];
                #pragma unroll
                for (int j = 0; j < 12; j++) wv[j] = Wi[(jb * 12 + j) * 65 + k];
                #pragma unroll
                for (int i = 0; i < 4; i++)
                    #pragma unroll
                    for (int j = 0; j < 12; j++)
                        acc[i][j] = fmaf(xv[i], wv[j], acc[i][j]);
            }
            #pragma unroll
            for (int i = 0; i < 4; i++)
                #pragma unroll
                for (int j = 0; j < 12; j++)
                    QKV[(lb * 4 + i) * 196 + jb * 12 + j] = acc[i][j] + bin[jb * 12 + j];
        }
        __syncthreads();

        // attention: thread = (query i, head h), online softmax
        {
            int i = t & 63, h = t >> 6;
            float q[16];
            #pragma unroll
            for (int c = 0; c < 16; c++) q[c] = QKV[i * 196 + h * 16 + c];
            float m = -1e30f, ssum = 0.f, acc[16];
            #pragma unroll
            for (int c = 0; c < 16; c++) acc[c] = 0.f;
            for (int j = 0; j < 64; j++) {
                float s = 0.f;
                #pragma unroll
                for (int c = 0; c < 16; c++) s = fmaf(q[c], QKV[j * 196 + 64 + h * 16 + c], s);
                s *= 0.25f;
                float nm = fmaxf(m, s);
                float corr = expf(m - nm);
                float w = expf(s - nm);
                ssum = ssum * corr + w;
                #pragma unroll
                for (int c = 0; c < 16; c++)
                    acc[c] = fmaf(acc[c], corr, w * QKV[j * 196 + 128 + h * 16 + c]);
                m = nm;
            }
            float inv = 1.f / ssum;
            #pragma unroll
            for (int c = 0; c < 16; c++) O[i * 65 + h * 16 + c] = acc[c] * inv;
        }
        __syncthreads();

        // out proj (thread: 4 rows x 4 cols) + fused epilogue / global writes
        {
            int lb = t >> 4, db = t & 15;
            float acc[4][4];
            #pragma unroll
            for (int i = 0; i < 4; i++)
                #pragma unroll
                for (int j = 0; j < 4; j++) acc[i][j] = 0.f;
            #pragma unroll 4
            for (int k = 0; k < 64; k++) {
                float ov[4], wv[4];
                #pragma unroll
                for (int i = 0; i < 4; i++) ov[i] = O[(lb * 4 + i) * 65 + k];
                #pragma unroll
                for (int j = 0; j < 4; j++) wv[j] = Wo[(db * 4 + j) * 65 + k];
                #pragma unroll
                for (int i = 0; i < 4; i++)
                    #pragma unroll
                    for (int j = 0; j < 4; j++)
                        acc[i][j] = fmaf(ov[i], wv[j], acc[i][j]);
            }
            int d0 = db * 4;
            #pragma unroll
            for (int i = 0; i < 4; i++) {
                int l = lb * 4 + i;
                int row = rows[l];
                float4 v;
                v.x = acc[i][0] + bout[d0 + 0];
                v.y = acc[i][1] + bout[d0 + 1];
                v.z = acc[i][2] + bout[d0 + 2];
                v.w = acc[i][3] + bout[d0 + 3];
                if (p == 0) {
                    *(float4*)&MUb[l * 64 + d0] = v;
                    *(float4*)&out_mu[(size_t)row * 128 + d0] = v;
                    *(float4*)&out_mu[(size_t)row * 128 + 64 + d0] =
                        *(const float4*)&g_inter_mu[g * 64 + d0];
                    *(float4*)&out_ac[(size_t)row * 640 + 512 + d0] =
                        *(const float4*)&g_inter_sample[g * 64 + d0];
                } else {
                    float4 st;
                    st.x = softplusf(v.x - 5.f);
                    st.y = softplusf(v.y - 5.f);
                    st.z = softplusf(v.z - 5.f);
                    st.w = softplusf(v.w - 5.f);
                    float4 mu4 = *(const float4*)&MUb[l * 64 + d0];
                    float4 ep  = *(const float4*)&eps_intra[(size_t)row * 64 + d0];
                    float4 samp;
                    samp.x = fmaf(st.x, ep.x, mu4.x);
                    samp.y = fmaf(st.y, ep.y, mu4.y);
                    samp.z = fmaf(st.z, ep.z, mu4.z);
                    samp.w = fmaf(st.w, ep.w, mu4.w);
                    *(float4*)&out_std[(size_t)row * 128 + d0] = st;
                    *(float4*)&out_std[(size_t)row * 128 + 64 + d0] =
                        *(const float4*)&g_inter_std[g * 64 + d0];
                    *(float4*)&out_ac[(size_t)row * 640 + 576 + d0] = samp;
                }
            }
        }
    }
}

// ---------------------------------------------------------------------------
extern "C" void kernel_launch(void* const* d_in, const int* in_sizes, int n_in,
                              void* d_out, int out_size)
{
    (void)in_sizes; (void)n_in; (void)out_size;
    const float* obs        = (const float*)d_in[0];
    const int*   sets       = (const int*)  d_in[1];
    const float* eps_intra  = (const float*)d_in[2];
    const float* eps_inter  = (const float*)d_in[3];
    const float* local_w    = (const float*)d_in[4];
    const float* local_b    = (const float*)d_in[5];
    const float* inter_emb_w= (const float*)d_in[6];
    const float* inter_emb_b= (const float*)d_in[7];
    const float* intra_emb_w= (const float*)d_in[8];
    const float* intra_emb_b= (const float*)d_in[9];
    const float* amu_in_w   = (const float*)d_in[10];
    const float* amu_in_b   = (const float*)d_in[11];
    const float* amu_out_w  = (const float*)d_in[12];
    const float* amu_out_b  = (const float*)d_in[13];
    const float* astd_in_w  = (const float*)d_in[14];
    const float* astd_in_b  = (const float*)d_in[15];
    const float* astd_out_w = (const float*)d_in[16];
    const float* astd_out_b = (const float*)d_in[17];
    const float* emu_in_w   = (const float*)d_in[18];
    const float* emu_in_b   = (const float*)d_in[19];
    const float* emu_out_w  = (const float*)d_in[20];
    const float* emu_out_b  = (const float*)d_in[21];
    const float* estd_in_w  = (const float*)d_in[22];
    const float* estd_in_b  = (const float*)d_in[23];
    const float* estd_out_w = (const float*)d_in[24];
    const float* estd_out_b = (const float*)d_in[25];
    const float* attset_w   = (const float*)d_in[26];
    const float* attset_b   = (const float*)d_in[27];

    float* out_ac  = (float*)d_out;
    float* out_mu  = out_ac + (size_t)NN * 640;
    float* out_std = out_mu + (size_t)NN * 128;

    const int k2_smem  = (64*65 + 192*65 + 192 + 64*196 + 64*65 + 64*65 + 64 + 64*64) * 4 + 64 * 4;
    const int k4b_smem = 2 * 1024 * 16 * 4;
    cudaFuncSetAttribute(k2_intra, cudaFuncAttributeMaxDynamicSharedMemorySize, k2_smem);
    cudaFuncSetAttribute(k4b_attn, cudaFuncAttributeMaxDynamicSharedMemorySize, k4b_smem);

    dim3 g1(512, 10);
    k1_embed<<<g1, 256>>>(obs, local_w, local_b, inter_emb_w, inter_emb_b,
                          intra_emb_w, intra_emb_b, out_ac);
    k3_pool<<<GG, 64>>>(sets, attset_w, attset_b);
    dim3 g4a(16, 2);
    k4a_qkv<<<g4a, 256>>>(emu_in_w, emu_in_b, estd_in_w, estd_in_b);
    dim3 g4b(16, 4, 2);
    k4b_attn<<<g4b, 64, k4b_smem>>>();
    k4c_proj<<<16, 256>>>(emu_out_w, emu_out_b, estd_out_w, estd_out_b, eps_inter);
    k2_intra<<<GG, 256, k2_smem>>>(sets,
                                   amu_in_w, amu_in_b, amu_out_w, amu_out_b,
                                   astd_in_w, astd_in_b, astd_out_w, astd_out_b,
                                   eps_intra, out_ac, out_mu, out_std);
}

// round 6
// speedup vs baseline: 1.3900x; 1.3900x over previous
#include <cuda_runtime.h>
#include <cuda_bf16.h>
#include <math.h>
#include <stdint.h>

#define NN 65536
#define GG 1024
#define SSZ 64
#define DD 64
#define OBSD 256
#define HIDD 512

// ---------------- scratch (device globals; no allocations allowed) ----------
__device__ __align__(16) float g_inter_emb[NN * DD];
__device__ __align__(16) float g_intra_emb[NN * DD];
__device__ __align__(16) float g_pooled[GG * DD];
__device__ __align__(16) float g_qkv[2][GG * 3 * DD];
__device__ __align__(16) float g_attno[2][GG * DD];
__device__ __align__(16) float g_inter_mu[GG * DD];
__device__ __align__(16) float g_inter_std[GG * DD];
__device__ __align__(16) float g_inter_sample[GG * DD];

// bf16 hi/lo split operands for the big GEMM
__device__ __align__(16) __nv_bfloat16 g_Ah[(size_t)NN * OBSD];
__device__ __align__(16) __nv_bfloat16 g_Al[(size_t)NN * OBSD];
__device__ __align__(16) __nv_bfloat16 g_Wh[640 * OBSD];
__device__ __align__(16) __nv_bfloat16 g_Wl[640 * OBSD];
__device__ float g_bias[640];

__device__ __forceinline__ float softplusf(float x) {
    return (x > 20.f) ? x : log1pf(expf(x));
}

__device__ __forceinline__ uint32_t smem_u32(const void* p) {
    uint32_t a;
    asm("{ .reg .u64 t; cvta.to.shared.u64 t, %1; cvt.u32.u64 %0, t; }" : "=r"(a) : "l"(p));
    return a;
}
__device__ __forceinline__ uint32_t swz128(uint32_t off) {
    return off ^ ((off >> 3) & 0x70);
}
__device__ __forceinline__ void ldm_x4(uint32_t* r, uint32_t addr) {
    asm volatile("ldmatrix.sync.aligned.m8n8.x4.shared.b16 {%0,%1,%2,%3}, [%4];"
        : "=r"(r[0]), "=r"(r[1]), "=r"(r[2]), "=r"(r[3]) : "r"(addr));
}
__device__ __forceinline__ void mma16816(float* d, const uint32_t* a, const uint32_t* b) {
    asm volatile(
        "mma.sync.aligned.m16n8k16.row.col.f32.bf16.bf16.f32 "
        "{%0,%1,%2,%3}, {%4,%5,%6,%7}, {%8,%9}, {%0,%1,%2,%3};"
        : "+f"(d[0]), "+f"(d[1]), "+f"(d[2]), "+f"(d[3])
        : "r"(a[0]), "r"(a[1]), "r"(a[2]), "r"(a[3]), "r"(b[0]), "r"(b[1]));
}

// ---------------------------------------------------------------------------
// K0a: split obs fp32 -> bf16 hi/lo
// ---------------------------------------------------------------------------
__global__ __launch_bounds__(256) void k0_split_A(const float4* __restrict__ obs4) {
    size_t i = (size_t)blockIdx.x * 256 + threadIdx.x;   // over NN*OBSD/4
    float4 v = obs4[i];
    size_t b = i * 4;
    __nv_bfloat16 h0 = __float2bfloat16(v.x);
    __nv_bfloat16 h1 = __float2bfloat16(v.y);
    __nv_bfloat16 h2 = __float2bfloat16(v.z);
    __nv_bfloat16 h3 = __float2bfloat16(v.w);
    __nv_bfloat16 l0 = __float2bfloat16(v.x - __bfloat162float(h0));
    __nv_bfloat16 l1 = __float2bfloat16(v.y - __bfloat162float(h1));
    __nv_bfloat16 l2 = __float2bfloat16(v.z - __bfloat162float(h2));
    __nv_bfloat16 l3 = __float2bfloat16(v.w - __bfloat162float(h3));
    *(__nv_bfloat162*)&g_Ah[b]     = __halves2bfloat162(h0, h1);
    *(__nv_bfloat162*)&g_Ah[b + 2] = __halves2bfloat162(h2, h3);
    *(__nv_bfloat162*)&g_Al[b]     = __halves2bfloat162(l0, l1);
    *(__nv_bfloat162*)&g_Al[b + 2] = __halves2bfloat162(l2, l3);
}

// K0b: pack weights [640][256] = [local(512); inter(64); intra(64)] + bias
__global__ __launch_bounds__(256) void k0_split_W(
    const float* __restrict__ lw, const float* __restrict__ lb,
    const float* __restrict__ iw, const float* __restrict__ ib,
    const float* __restrict__ tw, const float* __restrict__ tb)
{
    int row = blockIdx.x, col = threadIdx.x;
    const float* src; const float* bs; int r;
    if (row < 512)      { src = lw; bs = lb; r = row; }
    else if (row < 576) { src = iw; bs = ib; r = row - 512; }
    else                { src = tw; bs = tb; r = row - 576; }
    float x = src[r * OBSD + col];
    __nv_bfloat16 h = __float2bfloat16(x);
    g_Wh[row * OBSD + col] = h;
    g_Wl[row * OBSD + col] = __float2bfloat16(x - __bfloat162float(h));
    if (col == 0) g_bias[row] = bs[r];
}

// ---------------------------------------------------------------------------
// K1: mma.sync bf16-split GEMM  C[65536,640] = tanh(A @ W^T + b).
// grid 512, block 256 (8 warps = 4M x 2N). M-tile 128, N loop of 5 x 128,
// K chunks of 64 staged in SW128 smem, 3 HMMA products per k16 (hi/lo split).
// ---------------------------------------------------------------------------
#define K1_AH 0
#define K1_AL 16384
#define K1_BH 32768
#define K1_BL 49152
#define K1_SMEM 65536

__global__ __launch_bounds__(256) void k1_mma(float* __restrict__ out_ac)
{
    extern __shared__ char sm1[];
    uint32_t smb = smem_u32(sm1);
    int t = threadIdx.x;
    int lane = t & 31, wid = t >> 5;
    int mwarp = wid & 3, nwarp = wid >> 2;
    int row0 = blockIdx.x * 128;

    // staging indices
    int arow = t >> 1;
    int kseg = (t & 1);                 // 0/1 -> 32 bf16 halves of the 64-wide chunk

    // ldmatrix address offsets (within a 128B-row chunk image)
    // A: row = mwarp*32 + mt*16 + (lane&15), kbyte = ks*32 + (lane>>4)*16
    uint32_t a_row_im = (uint32_t)(mwarp * 32 + (lane & 15));
    uint32_t a_kb_im  = (uint32_t)((lane >> 4) * 16);
    // B: row = nwarp*64 + np*16 + ((lane>>4)&1)*8 + (lane&7), kbyte = ks*32 + ((lane>>3)&1)*16
    uint32_t b_row_im = (uint32_t)(nwarp * 64 + ((lane >> 4) & 1) * 8 + (lane & 7));
    uint32_t b_kb_im  = (uint32_t)(((lane >> 3) & 1) * 16);

    for (int nb = 0; nb < 5; nb++) {
        int cb = nb * 128;
        float acc[2][8][4];
        #pragma unroll
        for (int mt = 0; mt < 2; mt++)
            #pragma unroll
            for (int nt = 0; nt < 8; nt++)
                #pragma unroll
                for (int e = 0; e < 4; e++) acc[mt][nt][e] = 0.f;

        for (int ck = 0; ck < 4; ck++) {
            int k0 = ck * 64;
            // stage A/B hi+lo chunks [128 x 64 bf16] with SW128 swizzle
            {
                size_t aoff = (size_t)(row0 + arow) * OBSD + k0 + kseg * 32;
                size_t boff = (size_t)(cb + arow) * OBSD + k0 + kseg * 32;
                #pragma unroll
                for (int i = 0; i < 4; i++) {
                    uint32_t so = swz128((uint32_t)arow * 128 + kseg * 64 + i * 16);
                    *(float4*)(sm1 + K1_AH + so) = *(const float4*)&g_Ah[aoff + i * 8];
                    *(float4*)(sm1 + K1_AL + so) = *(const float4*)&g_Al[aoff + i * 8];
                    *(float4*)(sm1 + K1_BH + so) = *(const float4*)&g_Wh[boff + i * 8];
                    *(float4*)(sm1 + K1_BL + so) = *(const float4*)&g_Wl[boff + i * 8];
                }
            }
            __syncthreads();

            #pragma unroll
            for (int ks = 0; ks < 4; ks++) {
                uint32_t aH[2][4], aL[2][4];
                #pragma unroll
                for (int mt = 0; mt < 2; mt++) {
                    uint32_t off = swz128((a_row_im + mt * 16) * 128 + ks * 32 + a_kb_im);
                    ldm_x4(aH[mt], smb + K1_AH + off);
                    ldm_x4(aL[mt], smb + K1_AL + off);
                }
                uint32_t bH[4][4], bL[4][4];
                #pragma unroll
                for (int np = 0; np < 4; np++) {
                    uint32_t off = swz128((b_row_im + np * 16) * 128 + ks * 32 + b_kb_im);
                    ldm_x4(bH[np], smb + K1_BH + off);
                    ldm_x4(bL[np], smb + K1_BL + off);
                }
                #pragma unroll
                for (int mt = 0; mt < 2; mt++)
                    #pragma unroll
                    for (int np = 0; np < 4; np++) {
                        mma16816(acc[mt][np * 2 + 0], aH[mt], bH[np] + 0);
                        mma16816(acc[mt][np * 2 + 1], aH[mt], bH[np] + 2);
                        mma16816(acc[mt][np * 2 + 0], aH[mt], bL[np] + 0);
                        mma16816(acc[mt][np * 2 + 1], aH[mt], bL[np] + 2);
                        mma16816(acc[mt][np * 2 + 0], aL[mt], bH[np] + 0);
                        mma16816(acc[mt][np * 2 + 1], aL[mt], bH[np] + 2);
                    }
            }
            __syncthreads();
        }

        // epilogue: bias + tanh
        #pragma unroll
        for (int mt = 0; mt < 2; mt++) {
            int rbase = row0 + mwarp * 32 + mt * 16 + (lane >> 2);
            #pragma unroll
            for (int nt = 0; nt < 8; nt++) {
                int colT = nwarp * 64 + nt * 8 + (lane & 3) * 2;  // col within 128-tile
                int colg = cb + colT;
                float2 b2 = *(const float2*)&g_bias[colg];
                #pragma unroll
                for (int rh = 0; rh < 2; rh++) {
                    int row = rbase + rh * 8;
                    float2 o;
                    o.x = tanhf(acc[mt][nt][rh * 2 + 0] + b2.x);
                    o.y = tanhf(acc[mt][nt][rh * 2 + 1] + b2.y);
                    float* dst;
                    if (nb < 4)
                        dst = &out_ac[(size_t)row * 640 + colg];
                    else if (colT < 64)
                        dst = &g_inter_emb[(size_t)row * 64 + colT];
                    else
                        dst = &g_intra_emb[(size_t)row * 64 + (colT - 64)];
                    *(float2*)dst = o;
                }
            }
        }
        __syncthreads();
    }
}

// ---------------------------------------------------------------------------
// K3: softmax pooling per group. 1 block / group, 64 threads.
// ---------------------------------------------------------------------------
__global__ __launch_bounds__(64) void k3_pool(
    const int* __restrict__ sets,
    const float* __restrict__ aw, const float* __restrict__ ab)
{
    __shared__ float X[64][65];
    __shared__ float wgt[64];
    __shared__ int rows[64];
    __shared__ float wm[2], wsum[2];

    int t = threadIdx.x;
    int g = blockIdx.x;
    rows[t] = sets[g * 64 + t];
    __syncthreads();
    for (int l = 0; l < 64; l++)
        X[l][t] = g_inter_emb[(size_t)rows[l] * 64 + t];
    __syncthreads();

    float lg = ab[0];
    #pragma unroll 8
    for (int k = 0; k < 64; k++) lg = fmaf(X[t][k], aw[k], lg);

    float m = lg;
    #pragma unroll
    for (int o = 16; o; o >>= 1) m = fmaxf(m, __shfl_xor_sync(0xffffffffu, m, o));
    if ((t & 31) == 0) wm[t >> 5] = m;
    __syncthreads();
    m = fmaxf(wm[0], wm[1]);
    float e = expf(lg - m);
    float s = e;
    #pragma unroll
    for (int o = 16; o; o >>= 1) s += __shfl_xor_sync(0xffffffffu, s, o);
    if ((t & 31) == 0) wsum[t >> 5] = s;
    __syncthreads();
    s = wsum[0] + wsum[1];
    wgt[t] = e / s;
    __syncthreads();

    float acc = 0.f;
    #pragma unroll 8
    for (int k = 0; k < 64; k++) acc = fmaf(wgt[k], X[k][t], acc);
    g_pooled[g * 64 + t] = acc;
}

// ---------------------------------------------------------------------------
// K4a: inter QKV = pooled @ w_in^T + b.  grid (16, 2[mu/std]), 256 thr.
// ---------------------------------------------------------------------------
__global__ __launch_bounds__(256) void k4a_qkv(
    const float* __restrict__ wmi, const float* __restrict__ bmi,
    const float* __restrict__ wsi, const float* __restrict__ bsi)
{
    __shared__ float X[64][65];
    int t = threadIdx.x;
    int r0 = blockIdx.x * 64;
    int p = blockIdx.y;
    const float* Wi = p ? wsi : wmi;
    const float* bi = p ? bsi : bmi;

    {
        int l = t >> 2, c = (t & 3) * 16;
        #pragma unroll
        for (int i = 0; i < 4; i++) {
            float4 v = *(const float4*)&g_pooled[(r0 + l) * 64 + c + i * 4];
            X[l][c + i * 4 + 0] = v.x;
            X[l][c + i * 4 + 1] = v.y;
            X[l][c + i * 4 + 2] = v.z;
            X[l][c + i * 4 + 3] = v.w;
        }
    }
    __syncthreads();

    int l  = t & 63;
    int jb = t >> 6;
    for (int jj = 0; jj < 48; jj++) {
        int j = jb * 48 + jj;
        float acc = bi[j];
        #pragma unroll 8
        for (int k = 0; k < 64; k++) acc = fmaf(X[l][k], __ldg(&Wi[j * 64 + k]), acc);
        g_qkv[p][(r0 + l) * 192 + j] = acc;
    }
}

// ---------------------------------------------------------------------------
// K4b: inter attention (L=1024, dh=16). grid (16 qtiles, 4 heads, 2 passes),
// 512 threads: 8 key-chunks of 128 keys with partial online softmax + combine.
// ---------------------------------------------------------------------------
__global__ __launch_bounds__(512) void k4b_attn()
{
    extern __shared__ float sm4b[];
    float* Ks   = sm4b;                  // 1024*16
    float* Vs   = Ks + 1024 * 16;        // 1024*16
    float* pm   = Vs + 1024 * 16;        // 8*64
    float* ps   = pm + 8 * 64;           // 8*64
    float* pacc = ps + 8 * 64;           // 8*64*16

    int t  = threadIdx.x;
    int kc = t >> 6, qi = t & 63;
    int q0 = blockIdx.x * 64;
    int h  = blockIdx.y;
    int p  = blockIdx.z;
    const float* QKV = g_qkv[p];

    for (int r = t; r < 1024; r += 512) {
        #pragma unroll
        for (int i = 0; i < 4; i++) {
            *(float4*)&Ks[r * 16 + i * 4] =
                *(const float4*)&QKV[(size_t)r * 192 + 64 + h * 16 + i * 4];
            *(float4*)&Vs[r * 16 + i * 4] =
                *(const float4*)&QKV[(size_t)r * 192 + 128 + h * 16 + i * 4];
        }
    }
    __syncthreads();

    float q[16];
    #pragma unroll
    for (int i = 0; i < 16; i++) q[i] = QKV[(size_t)(q0 + qi) * 192 + h * 16 + i];

    float m = -1e30f, ssum = 0.f, acc[16];
    #pragma unroll
    for (int i = 0; i < 16; i++) acc[i] = 0.f;

    int jbase = kc * 128;
    for (int j = jbase; j < jbase + 128; j++) {
        float s = 0.f;
        #pragma unroll
        for (int c = 0; c < 16; c++) s = fmaf(q[c], Ks[j * 16 + c], s);
        s *= 0.25f;
        float nm = fmaxf(m, s);
        float corr = expf(m - nm);
        float w = expf(s - nm);
        ssum = ssum * corr + w;
        #pragma unroll
        for (int c = 0; c < 16; c++) acc[c] = fmaf(acc[c], corr, w * Vs[j * 16 + c]);
        m = nm;
    }
    pm[kc * 64 + qi] = m;
    ps[kc * 64 + qi] = ssum;
    #pragma unroll
    for (int c = 0; c < 16; c++) pacc[(kc * 64 + qi) * 16 + c] = acc[c];
    __syncthreads();

    if (t < 64) {
        float gm = -1e30f;
        #pragma unroll
        for (int i = 0; i < 8; i++) gm = fmaxf(gm, pm[i * 64 + t]);
        float s = 0.f, o[16];
        #pragma unroll
        for (int c = 0; c < 16; c++) o[c] = 0.f;
        #pragma unroll
        for (int i = 0; i < 8; i++) {
            float w = expf(pm[i * 64 + t] - gm);
            s = fmaf(ps[i * 64 + t], w, s);
            #pragma unroll
            for (int c = 0; c < 16; c++)
                o[c] = fmaf(pacc[(i * 64 + t) * 16 + c], w, o[c]);
        }
        float inv = 1.f / s;
        #pragma unroll
        for (int c = 0; c < 16; c++)
            g_attno[p][(size_t)(q0 + t) * 64 + h * 16 + c] = o[c] * inv;
    }
}

// ---------------------------------------------------------------------------
// K4c: inter out-proj, softplus, sample. grid 16, 256 threads.
// ---------------------------------------------------------------------------
__global__ __launch_bounds__(256) void k4c_proj(
    const float* __restrict__ wmo, const float* __restrict__ bmo,
    const float* __restrict__ wso, const float* __restrict__ bso,
    const float* __restrict__ eps_inter)
{
    __shared__ float Om[64][65];
    __shared__ float Os[64][65];
    int t = threadIdx.x;
    int r0 = blockIdx.x * 64;
    {
        int l = t >> 2, c = (t & 3) * 16;
        for (int i = 0; i < 16; i++) {
            Om[l][c + i] = g_attno[0][(size_t)(r0 + l) * 64 + c + i];
            Os[l][c + i] = g_attno[1][(size_t)(r0 + l) * 64 + c + i];
        }
    }
    __syncthreads();

    int lb = t >> 4, db = t & 15;
    float am[4][4], as[4][4];
    #pragma unroll
    for (int i = 0; i < 4; i++)
        #pragma unroll
        for (int j = 0; j < 4; j++) { am[i][j] = 0.f; as[i][j] = 0.f; }

    #pragma unroll 4
    for (int k = 0; k < 64; k++) {
        float om[4], os[4], wmv[4], wsv[4];
        #pragma unroll
        for (int i = 0; i < 4; i++) { om[i] = Om[lb * 4 + i][k]; os[i] = Os[lb * 4 + i][k]; }
        #pragma unroll
        for (int j = 0; j < 4; j++) {
            wmv[j] = __ldg(&wmo[(db * 4 + j) * 64 + k]);
            wsv[j] = __ldg(&wso[(db * 4 + j) * 64 + k]);
        }
        #pragma unroll
        for (int i = 0; i < 4; i++)
            #pragma unroll
            for (int j = 0; j < 4; j++) {
                am[i][j] = fmaf(om[i], wmv[j], am[i][j]);
                as[i][j] = fmaf(os[i], wsv[j], as[i][j]);
            }
    }
    #pragma unroll
    for (int i = 0; i < 4; i++) {
        int gi = r0 + lb * 4 + i;
        #pragma unroll
        for (int j = 0; j < 4; j++) {
            int d = db * 4 + j;
            float mu  = am[i][j] + bmo[d];
            float st  = softplusf(as[i][j] + bso[d] - 5.f);
            g_inter_mu[gi * 64 + d] = mu;
            g_inter_std[gi * 64 + d] = st;
            g_inter_sample[gi * 64 + d] = fmaf(st, eps_inter[gi * 64 + d], mu);
        }
    }
}

// ---------------------------------------------------------------------------
// K2: intra MHA per group (mu then std), fused with ALL final scatter writes.
// ---------------------------------------------------------------------------
__global__ __launch_bounds__(256) void k2_intra(
    const int* __restrict__ sets,
    const float* __restrict__ wmi, const float* __restrict__ bmi,
    const float* __restrict__ wmo, const float* __restrict__ bmo,
    const float* __restrict__ wsi, const float* __restrict__ bsi,
    const float* __restrict__ wso, const float* __restrict__ bso,
    const float* __restrict__ eps_intra,
    float* __restrict__ out_ac, float* __restrict__ out_mu, float* __restrict__ out_std)
{
    extern __shared__ float sm[];
    float* X    = sm;                  // [64][65]
    float* Wi   = X + 64 * 65;         // [192][65]
    float* bin  = Wi + 192 * 65;       // [192]
    float* QKV  = bin + 192;           // [64][196]
    float* O    = QKV + 64 * 196;      // [64][65]
    float* Wo   = O + 64 * 65;         // [64][65]
    float* bout = Wo + 64 * 65;        // [64]
    float* MUb  = bout + 64;           // [64][64]
    int*   rows = (int*)(MUb + 64 * 64); // [64]

    int t = threadIdx.x;
    int g = blockIdx.x;
    if (t < 64) rows[t] = sets[g * 64 + t];
    __syncthreads();
    {
        int l = t >> 2, c = (t & 3) * 16;
        const float* src = &g_intra_emb[(size_t)rows[l] * 64 + c];
        #pragma unroll
        for (int i = 0; i < 4; i++) {
            float4 v = *(const float4*)&src[i * 4];
            X[l * 65 + c + i * 4 + 0] = v.x;
            X[l * 65 + c + i * 4 + 1] = v.y;
            X[l * 65 + c + i * 4 + 2] = v.z;
            X[l * 65 + c + i * 4 + 3] = v.w;
        }
    }

    for (int p = 0; p < 2; p++) {
        const float* wIn  = p ? wsi : wmi;
        const float* bIn  = p ? bsi : bmi;
        const float* wOut = p ? wso : wmo;
        const float* bOut = p ? bso : bmo;
        __syncthreads();
        for (int v = t; v < 3072; v += 256) {
            int j = v >> 4; int cv = (v & 15) * 4;
            float4 w4 = *(const float4*)&wIn[j * 64 + cv];
            Wi[j * 65 + cv + 0] = w4.x; Wi[j * 65 + cv + 1] = w4.y;
            Wi[j * 65 + cv + 2] = w4.z; Wi[j * 65 + cv + 3] = w4.w;
        }
        if (t < 192) bin[t] = bIn[t];
        for (int v = t; v < 1024; v += 256) {
            int j = v >> 4; int cv = (v & 15) * 4;
            float4 w4 = *(const float4*)&wOut[j * 64 + cv];
            Wo[j * 65 + cv + 0] = w4.x; Wo[j * 65 + cv + 1] = w4.y;
            Wo[j * 65 + cv + 2] = w4.z; Wo[j * 65 + cv + 3] = w4.w;
        }
        if (t < 64) bout[t] = bOut[t];
        __syncthreads();

        {
            int lb = t >> 4, jb = t & 15;
            float acc[4][12];
            #pragma unroll
            for (int i = 0; i < 4; i++)
                #pragma unroll
                for (int j = 0; j < 12; j++) acc[i][j] = 0.f;
            #pragma unroll 4
            for (int k = 0; k < 64; k++) {
                float xv[4], wv[12];
                #pragma unroll
                for (int i = 0; i < 4; i++) xv[i] = X[(lb * 4 + i) * 65 + k];
                #pragma unroll
                for (int j = 0; j < 12; j++) wv[j] = Wi[(jb * 12 + j) * 65 + k];
                #pragma unroll
                for (int i = 0; i < 4; i++)
                    #pragma unroll
                    for (int j = 0; j < 12; j++)
                        acc[i][j] = fmaf(xv[i], wv[j], acc[i][j]);
            }
            #pragma unroll
            for (int i = 0; i < 4; i++)
                #pragma unroll
                for (int j = 0; j < 12; j++)
                    QKV[(lb * 4 + i) * 196 + jb * 12 + j] = acc[i][j] + bin[jb * 12 + j];
        }
        __syncthreads();

        {
            int i = t & 63, h = t >> 6;
            float q[16];
            #pragma unroll
            for (int c = 0; c < 16; c++) q[c] = QKV[i * 196 + h * 16 + c];
            float m = -1e30f, ssum = 0.f, acc[16];
            #pragma unroll
            for (int c = 0; c < 16; c++) acc[c] = 0.f;
            for (int j = 0; j < 64; j++) {
                float s = 0.f;
                #pragma unroll
                for (int c = 0; c < 16; c++) s = fmaf(q[c], QKV[j * 196 + 64 + h * 16 + c], s);
                s *= 0.25f;
                float nm = fmaxf(m, s);
                float corr = expf(m - nm);
                float w = expf(s - nm);
                ssum = ssum * corr + w;
                #pragma unroll
                for (int c = 0; c < 16; c++)
                    acc[c] = fmaf(acc[c], corr, w * QKV[j * 196 + 128 + h * 16 + c]);
                m = nm;
            }
            float inv = 1.f / ssum;
            #pragma unroll
            for (int c = 0; c < 16; c++) O[i * 65 + h * 16 + c] = acc[c] * inv;
        }
        __syncthreads();

        {
            int lb = t >> 4, db = t & 15;
            float acc[4][4];
            #pragma unroll
            for (int i = 0; i < 4; i++)
                #pragma unroll
                for (int j = 0; j < 4; j++) acc[i][j] = 0.f;
            #pragma unroll 4
            for (int k = 0; k < 64; k++) {
                float ov[4], wv[4];
                #pragma unroll
                for (int i = 0; i < 4; i++) ov[i] = O[(lb * 4 + i) * 65 + k];
                #pragma unroll
                for (int j = 0; j < 4; j++) wv[j] = Wo[(db * 4 + j) * 65 + k];
                #pragma unroll
                for (int i = 0; i < 4; i++)
                    #pragma unroll
                    for (int j = 0; j < 4; j++)
                        acc[i][j] = fmaf(ov[i], wv[j], acc[i][j]);
            }
            int d0 = db * 4;
            #pragma unroll
            for (int i = 0; i < 4; i++) {
                int l = lb * 4 + i;
                int row = rows[l];
                float4 v;
                v.x = acc[i][0] + bout[d0 + 0];
                v.y = acc[i][1] + bout[d0 + 1];
                v.z = acc[i][2] + bout[d0 + 2];
                v.w = acc[i][3] + bout[d0 + 3];
                if (p == 0) {
                    *(float4*)&MUb[l * 64 + d0] = v;
                    *(float4*)&out_mu[(size_t)row * 128 + d0] = v;
                    *(float4*)&out_mu[(size_t)row * 128 + 64 + d0] =
                        *(const float4*)&g_inter_mu[g * 64 + d0];
                    *(float4*)&out_ac[(size_t)row * 640 + 512 + d0] =
                        *(const float4*)&g_inter_sample[g * 64 + d0];
                } else {
                    float4 st;
                    st.x = softplusf(v.x - 5.f);
                    st.y = softplusf(v.y - 5.f);
                    st.z = softplusf(v.z - 5.f);
                    st.w = softplusf(v.w - 5.f);
                    float4 mu4 = *(const float4*)&MUb[l * 64 + d0];
                    float4 ep  = *(const float4*)&eps_intra[(size_t)row * 64 + d0];
                    float4 samp;
                    samp.x = fmaf(st.x, ep.x, mu4.x);
                    samp.y = fmaf(st.y, ep.y, mu4.y);
                    samp.z = fmaf(st.z, ep.z, mu4.z);
                    samp.w = fmaf(st.w, ep.w, mu4.w);
                    *(float4*)&out_std[(size_t)row * 128 + d0] = st;
                    *(float4*)&out_std[(size_t)row * 128 + 64 + d0] =
                        *(const float4*)&g_inter_std[g * 64 + d0];
                    *(float4*)&out_ac[(size_t)row * 640 + 576 + d0] = samp;
                }
            }
        }
    }
}

// ---------------------------------------------------------------------------
extern "C" void kernel_launch(void* const* d_in, const int* in_sizes, int n_in,
                              void* d_out, int out_size)
{
    (void)in_sizes; (void)n_in; (void)out_size;
    const float* obs        = (const float*)d_in[0];
    const int*   sets       = (const int*)  d_in[1];
    const float* eps_intra  = (const float*)d_in[2];
    const float* eps_inter  = (const float*)d_in[3];
    const float* local_w    = (const float*)d_in[4];
    const float* local_b    = (const float*)d_in[5];
    const float* inter_emb_w= (const float*)d_in[6];
    const float* inter_emb_b= (const float*)d_in[7];
    const float* intra_emb_w= (const float*)d_in[8];
    const float* intra_emb_b= (const float*)d_in[9];
    const float* amu_in_w   = (const float*)d_in[10];
    const float* amu_in_b   = (const float*)d_in[11];
    const float* amu_out_w  = (const float*)d_in[12];
    const float* amu_out_b  = (const float*)d_in[13];
    const float* astd_in_w  = (const float*)d_in[14];
    const float* astd_in_b  = (const float*)d_in[15];
    const float* astd_out_w = (const float*)d_in[16];
    const float* astd_out_b = (const float*)d_in[17];
    const float* emu_in_w   = (const float*)d_in[18];
    const float* emu_in_b   = (const float*)d_in[19];
    const float* emu_out_w  = (const float*)d_in[20];
    const float* emu_out_b  = (const float*)d_in[21];
    const float* estd_in_w  = (const float*)d_in[22];
    const float* estd_in_b  = (const float*)d_in[23];
    const float* estd_out_w = (const float*)d_in[24];
    const float* estd_out_b = (const float*)d_in[25];
    const float* attset_w   = (const float*)d_in[26];
    const float* attset_b   = (const float*)d_in[27];

    float* out_ac  = (float*)d_out;
    float* out_mu  = out_ac + (size_t)NN * 640;
    float* out_std = out_mu + (size_t)NN * 128;

    const int k2_smem  = (64*65 + 192*65 + 192 + 64*196 + 64*65 + 64*65 + 64 + 64*64) * 4 + 64 * 4;
    const int k4b_smem = (2 * 1024 * 16 + 8 * 64 * 2 + 8 * 64 * 16) * 4;
    cudaFuncSetAttribute(k2_intra, cudaFuncAttributeMaxDynamicSharedMemorySize, k2_smem);
    cudaFuncSetAttribute(k4b_attn, cudaFuncAttributeMaxDynamicSharedMemorySize, k4b_smem);
    cudaFuncSetAttribute(k1_mma, cudaFuncAttributeMaxDynamicSharedMemorySize, K1_SMEM);

    // split inputs into bf16 hi/lo
    k0_split_A<<<(NN * OBSD / 4 + 255) / 256, 256>>>((const float4*)obs);
    k0_split_W<<<640, 256>>>(local_w, local_b, inter_emb_w, inter_emb_b,
                             intra_emb_w, intra_emb_b);

    k1_mma<<<512, 256, K1_SMEM>>>(out_ac);

    k3_pool<<<GG, 64>>>(sets, attset_w, attset_b);
    dim3 g4a(16, 2);
    k4a_qkv<<<g4a, 256>>>(emu_in_w, emu_in_b, estd_in_w, estd_in_b);
    dim3 g4b(16, 4, 2);
    k4b_attn<<<g4b, 512, k4b_smem>>>();
    k4c_proj<<<16, 256>>>(emu_out_w, emu_out_b, estd_out_w, estd_out_b, eps_inter);
    k2_intra<<<GG, 256, k2_smem>>>(sets,
                                   amu_in_w, amu_in_b, amu_out_w, amu_out_b,
                                   astd_in_w, astd_in_b, astd_out_w, astd_out_b,
                                   eps_intra, out_ac, out_mu, out_std);
}

// round 8
// speedup vs baseline: 2.3567x; 1.6955x over previous
#include <cuda_runtime.h>
#include <cuda_bf16.h>
#include <math.h>
#include <stdint.h>

#define NN 65536
#define GG 1024
#define SSZ 64
#define DD 64
#define OBSD 256
#define HIDD 512

// ---------------- scratch (device globals; no allocations allowed) ----------
__device__ __align__(16) float g_inter_emb[NN * DD];
__device__ __align__(16) float g_pooled[GG * DD];
__device__ __align__(16) float g_qkv[2][GG * 3 * DD];
__device__ __align__(16) float g_attno[2][GG * DD];
__device__ __align__(16) float g_inter_mu[GG * DD];
__device__ __align__(16) float g_inter_std[GG * DD];
__device__ __align__(16) float g_inter_sample[GG * DD];

// bf16 hi/lo split operands
__device__ __align__(16) __nv_bfloat16 g_Ah[(size_t)NN * OBSD];
__device__ __align__(16) __nv_bfloat16 g_Al[(size_t)NN * OBSD];
__device__ __align__(16) __nv_bfloat16 g_Wh[640 * OBSD];
__device__ __align__(16) __nv_bfloat16 g_Wl[640 * OBSD];
__device__ float g_bias[640];

// intra_emb as bf16 hi/lo (input to k2a GEMM)
__device__ __align__(16) __nv_bfloat16 g_Eh[(size_t)NN * DD];
__device__ __align__(16) __nv_bfloat16 g_El[(size_t)NN * DD];
// packed intra in-proj weights [384=192mu+192std][64] hi/lo + bias
__device__ __align__(16) __nv_bfloat16 g_Wqh[384 * DD];
__device__ __align__(16) __nv_bfloat16 g_Wql[384 * DD];
__device__ float g_qbias[384];
// QKV (bias included) for all agents: [65536][384] (0..191 mu, 192..383 std)
__device__ __align__(16) float g_qkv_all[(size_t)NN * 384];

__device__ __forceinline__ float softplusf(float x) {
    return (x > 20.f) ? x : log1pf(expf(x));
}

__device__ __forceinline__ uint32_t smem_u32(const void* p) {
    uint32_t a;
    asm("{ .reg .u64 t; cvta.to.shared.u64 t, %1; cvt.u32.u64 %0, t; }" : "=r"(a) : "l"(p));
    return a;
}
__device__ __forceinline__ uint32_t swz128(uint32_t off) {
    return off ^ ((off >> 3) & 0x70);
}
__device__ __forceinline__ void ldm_x4(uint32_t* r, uint32_t addr) {
    asm volatile("ldmatrix.sync.aligned.m8n8.x4.shared.b16 {%0,%1,%2,%3}, [%4];"
        : "=r"(r[0]), "=r"(r[1]), "=r"(r[2]), "=r"(r[3]) : "r"(addr));
}
__device__ __forceinline__ void mma16816(float* d, const uint32_t* a, const uint32_t* b) {
    asm volatile(
        "mma.sync.aligned.m16n8k16.row.col.f32.bf16.bf16.f32 "
        "{%0,%1,%2,%3}, {%4,%5,%6,%7}, {%8,%9}, {%0,%1,%2,%3};"
        : "+f"(d[0]), "+f"(d[1]), "+f"(d[2]), "+f"(d[3])
        : "r"(a[0]), "r"(a[1]), "r"(a[2]), "r"(a[3]), "r"(b[0]), "r"(b[1]));
}
__device__ __forceinline__ void cpasync16(uint32_t dst, const void* src) {
    asm volatile("cp.async.cg.shared.global [%0], [%1], 16;" :: "r"(dst), "l"(src));
}
#define CP_COMMIT() asm volatile("cp.async.commit_group;" ::: "memory")
#define CP_WAIT1()  asm volatile("cp.async.wait_group 1;" ::: "memory")
#define CP_WAIT0()  asm volatile("cp.async.wait_group 0;" ::: "memory")

// ---------------------------------------------------------------------------
// K0a: split obs fp32 -> bf16 hi/lo
// ---------------------------------------------------------------------------
__global__ __launch_bounds__(256) void k0_split_A(const float4* __restrict__ obs4) {
    size_t i = (size_t)blockIdx.x * 256 + threadIdx.x;
    float4 v = obs4[i];
    size_t b = i * 4;
    __nv_bfloat16 h0 = __float2bfloat16(v.x);
    __nv_bfloat16 h1 = __float2bfloat16(v.y);
    __nv_bfloat16 h2 = __float2bfloat16(v.z);
    __nv_bfloat16 h3 = __float2bfloat16(v.w);
    __nv_bfloat16 l0 = __float2bfloat16(v.x - __bfloat162float(h0));
    __nv_bfloat16 l1 = __float2bfloat16(v.y - __bfloat162float(h1));
    __nv_bfloat16 l2 = __float2bfloat16(v.z - __bfloat162float(h2));
    __nv_bfloat16 l3 = __float2bfloat16(v.w - __bfloat162float(h3));
    *(__nv_bfloat162*)&g_Ah[b]     = __halves2bfloat162(h0, h1);
    *(__nv_bfloat162*)&g_Ah[b + 2] = __halves2bfloat162(h2, h3);
    *(__nv_bfloat162*)&g_Al[b]     = __halves2bfloat162(l0, l1);
    *(__nv_bfloat162*)&g_Al[b + 2] = __halves2bfloat162(l2, l3);
}

// K0b: pack embed weights [640][256] = [local(512); inter(64); intra(64)] + bias
__global__ __launch_bounds__(256) void k0_split_W(
    const float* __restrict__ lw, const float* __restrict__ lb,
    const float* __restrict__ iw, const float* __restrict__ ib,
    const float* __restrict__ tw, const float* __restrict__ tb)
{
    int row = blockIdx.x, col = threadIdx.x;
    const float* src; const float* bs; int r;
    if (row < 512)      { src = lw; bs = lb; r = row; }
    else if (row < 576) { src = iw; bs = ib; r = row - 512; }
    else                { src = tw; bs = tb; r = row - 576; }
    float x = src[r * OBSD + col];
    __nv_bfloat16 h = __float2bfloat16(x);
    g_Wh[row * OBSD + col] = h;
    g_Wl[row * OBSD + col] = __float2bfloat16(x - __bfloat162float(h));
    if (col == 0) g_bias[row] = bs[r];
}

// K0c: pack intra in-proj weights [384][64] (mu 0..191, std 192..383) + bias
__global__ __launch_bounds__(64) void k0_split_Wq(
    const float* __restrict__ wmi, const float* __restrict__ bmi,
    const float* __restrict__ wsi, const float* __restrict__ bsi)
{
    int row = blockIdx.x, col = threadIdx.x;
    const float* src; const float* bs; int r;
    if (row < 192) { src = wmi; bs = bmi; r = row; }
    else           { src = wsi; bs = bsi; r = row - 192; }
    float x = src[r * 64 + col];
    __nv_bfloat16 h = __float2bfloat16(x);
    g_Wqh[row * 64 + col] = h;
    g_Wql[row * 64 + col] = __float2bfloat16(x - __bfloat162float(h));
    if (col == 0) g_qbias[row] = bs[r];
}

// ---------------------------------------------------------------------------
// K1: mma.sync bf16-split GEMM  C[65536,640] = tanh(A @ W^T + b).
// grid 512, block 256 (8 warps = 4M x 2N). M-tile 128, N loop 5 x 128,
// K chunks of 64, cp.async double-buffered staging.
// Last N-tile: cols 0..63 -> g_inter_emb (fp32), 64..127 -> g_Eh/g_El (bf16 split).
// ---------------------------------------------------------------------------
#define K1_AH 0
#define K1_AL 16384
#define K1_BH 32768
#define K1_BL 49152
#define K1_BUF 65536
#define K1_SMEM (2 * K1_BUF)

__global__ __launch_bounds__(256) void k1_mma(float* __restrict__ out_ac)
{
    extern __shared__ char sm1[];
    uint32_t smb = smem_u32(sm1);
    int t = threadIdx.x;
    int lane = t & 31, wid = t >> 5;
    int mwarp = wid & 3, nwarp = wid >> 2;
    int row0 = blockIdx.x * 128;

    int arow = t >> 1;
    int kseg = (t & 1);

    uint32_t a_row_im = (uint32_t)(mwarp * 32 + (lane & 15));
    uint32_t a_kb_im  = (uint32_t)((lane >> 4) * 16);
    uint32_t b_row_im = (uint32_t)(nwarp * 64 + ((lane >> 4) & 1) * 8 + (lane & 7));
    uint32_t b_kb_im  = (uint32_t)(((lane >> 3) & 1) * 16);

    auto stage = [&](int buf, int nb, int ck) {
        int k0 = ck * 64, cb = nb * 128;
        size_t aoff = (size_t)(row0 + arow) * OBSD + k0 + kseg * 32;
        size_t boff = (size_t)(cb + arow) * OBSD + k0 + kseg * 32;
        uint32_t base = smb + buf * K1_BUF;
        #pragma unroll
        for (int i = 0; i < 4; i++) {
            uint32_t so = swz128((uint32_t)arow * 128 + kseg * 64 + i * 16);
            cpasync16(base + K1_AH + so, &g_Ah[aoff + i * 8]);
            cpasync16(base + K1_AL + so, &g_Al[aoff + i * 8]);
            cpasync16(base + K1_BH + so, &g_Wh[boff + i * 8]);
            cpasync16(base + K1_BL + so, &g_Wl[boff + i * 8]);
        }
    };

    float acc[2][8][4];
    stage(0, 0, 0);
    CP_COMMIT();

    for (int c = 0; c < 20; c++) {
        int nb = c >> 2, ck = c & 3, buf = c & 1;
        if (c + 1 < 20) {
            stage(buf ^ 1, (c + 1) >> 2, (c + 1) & 3);
            CP_COMMIT();
            CP_WAIT1();
        } else {
            CP_WAIT0();
        }
        __syncthreads();

        if (ck == 0) {
            #pragma unroll
            for (int mt = 0; mt < 2; mt++)
                #pragma unroll
                for (int nt = 0; nt < 8; nt++)
                    #pragma unroll
                    for (int e = 0; e < 4; e++) acc[mt][nt][e] = 0.f;
        }

        uint32_t base = smb + buf * K1_BUF;
        #pragma unroll
        for (int ks = 0; ks < 4; ks++) {
            uint32_t aH[2][4], aL[2][4];
            #pragma unroll
            for (int mt = 0; mt < 2; mt++) {
                uint32_t off = swz128((a_row_im + mt * 16) * 128 + ks * 32 + a_kb_im);
                ldm_x4(aH[mt], base + K1_AH + off);
                ldm_x4(aL[mt], base + K1_AL + off);
            }
            uint32_t bH[4][4], bL[4][4];
            #pragma unroll
            for (int np = 0; np < 4; np++) {
                uint32_t off = swz128((b_row_im + np * 16) * 128 + ks * 32 + b_kb_im);
                ldm_x4(bH[np], base + K1_BH + off);
                ldm_x4(bL[np], base + K1_BL + off);
            }
            #pragma unroll
            for (int mt = 0; mt < 2; mt++)
                #pragma unroll
                for (int np = 0; np < 4; np++) {
                    mma16816(acc[mt][np * 2 + 0], aH[mt], bH[np] + 0);
                    mma16816(acc[mt][np * 2 + 1], aH[mt], bH[np] + 2);
                    mma16816(acc[mt][np * 2 + 0], aH[mt], bL[np] + 0);
                    mma16816(acc[mt][np * 2 + 1], aH[mt], bL[np] + 2);
                    mma16816(acc[mt][np * 2 + 0], aL[mt], bH[np] + 0);
                    mma16816(acc[mt][np * 2 + 1], aL[mt], bH[np] + 2);
                }
        }
        __syncthreads();

        if (ck == 3) {
            int cb = nb * 128;
            #pragma unroll
            for (int mt = 0; mt < 2; mt++) {
                int rbase = row0 + mwarp * 32 + mt * 16 + (lane >> 2);
                #pragma unroll
                for (int nt = 0; nt < 8; nt++) {
                    int colT = nwarp * 64 + nt * 8 + (lane & 3) * 2;
                    int colg = cb + colT;
                    float2 b2 = *(const float2*)&g_bias[colg];
                    #pragma unroll
                    for (int rh = 0; rh < 2; rh++) {
                        int row = rbase + rh * 8;
                        float2 o;
                        o.x = tanhf(acc[mt][nt][rh * 2 + 0] + b2.x);
                        o.y = tanhf(acc[mt][nt][rh * 2 + 1] + b2.y);
                        if (nb < 4) {
                            *(float2*)&out_ac[(size_t)row * 640 + colg] = o;
                        } else if (colT < 64) {
                            *(float2*)&g_inter_emb[(size_t)row * 64 + colT] = o;
                        } else {
                            int d = colT - 64;
                            __nv_bfloat16 h0 = __float2bfloat16(o.x);
                            __nv_bfloat16 h1 = __float2bfloat16(o.y);
                            __nv_bfloat16 l0 = __float2bfloat16(o.x - __bfloat162float(h0));
                            __nv_bfloat16 l1 = __float2bfloat16(o.y - __bfloat162float(h1));
                            *(__nv_bfloat162*)&g_Eh[(size_t)row * 64 + d] = __halves2bfloat162(h0, h1);
                            *(__nv_bfloat162*)&g_El[(size_t)row * 64 + d] = __halves2bfloat162(l0, l1);
                        }
                    }
                }
            }
        }
    }
}

// ---------------------------------------------------------------------------
// K2a: mma.sync bf16-split GEMM  QKV_all[65536,384] = E @ Wq^T + qbias.
// grid 512, block 256 (8 warps = 4M x 2N). M-tile 128, N loop 3 x 128, K=64.
// ---------------------------------------------------------------------------
#define K2A_AH 0
#define K2A_AL 16384
#define K2A_BH 32768
#define K2A_BL 49152
#define K2A_SMEM 65536

__global__ __launch_bounds__(256) void k2a_qkv_gemm()
{
    extern __shared__ char sm2[];
    uint32_t smb = smem_u32(sm2);
    int t = threadIdx.x;
    int lane = t & 31, wid = t >> 5;
    int mwarp = wid & 3, nwarp = wid >> 2;
    int row0 = blockIdx.x * 128;

    int arow = t >> 1;
    int kseg = (t & 1);

    uint32_t a_row_im = (uint32_t)(mwarp * 32 + (lane & 15));
    uint32_t a_kb_im  = (uint32_t)((lane >> 4) * 16);
    uint32_t b_row_im = (uint32_t)(nwarp * 64 + ((lane >> 4) & 1) * 8 + (lane & 7));
    uint32_t b_kb_im  = (uint32_t)(((lane >> 3) & 1) * 16);

    // stage A hi/lo (once)
    {
        size_t aoff = (size_t)(row0 + arow) * 64 + kseg * 32;
        #pragma unroll
        for (int i = 0; i < 4; i++) {
            uint32_t so = swz128((uint32_t)arow * 128 + kseg * 64 + i * 16);
            *(float4*)(sm2 + K2A_AH + so) = *(const float4*)&g_Eh[aoff + i * 8];
            *(float4*)(sm2 + K2A_AL + so) = *(const float4*)&g_El[aoff + i * 8];
        }
    }

    for (int nb = 0; nb < 3; nb++) {
        int cb = nb * 128;
        {
            size_t boff = (size_t)(cb + arow) * 64 + kseg * 32;
            #pragma unroll
            for (int i = 0; i < 4; i++) {
                uint32_t so = swz128((uint32_t)arow * 128 + kseg * 64 + i * 16);
                *(float4*)(sm2 + K2A_BH + so) = *(const float4*)&g_Wqh[boff + i * 8];
                *(float4*)(sm2 + K2A_BL + so) = *(const float4*)&g_Wql[boff + i * 8];
            }
        }
        __syncthreads();

        float acc[2][8][4];
        #pragma unroll
        for (int mt = 0; mt < 2; mt++)
            #pragma unroll
            for (int nt = 0; nt < 8; nt++)
                #pragma unroll
                for (int e = 0; e < 4; e++) acc[mt][nt][e] = 0.f;

        #pragma unroll
        for (int ks = 0; ks < 4; ks++) {
            uint32_t aH[2][4], aL[2][4];
            #pragma unroll
            for (int mt = 0; mt < 2; mt++) {
                uint32_t off = swz128((a_row_im + mt * 16) * 128 + ks * 32 + a_kb_im);
                ldm_x4(aH[mt], smb + K2A_AH + off);
                ldm_x4(aL[mt], smb + K2A_AL + off);
            }
            uint32_t bH[4][4], bL[4][4];
            #pragma unroll
            for (int np = 0; np < 4; np++) {
                uint32_t off = swz128((b_row_im + np * 16) * 128 + ks * 32 + b_kb_im);
                ldm_x4(bH[np], smb + K2A_BH + off);
                ldm_x4(bL[np], smb + K2A_BL + off);
            }
            #pragma unroll
            for (int mt = 0; mt < 2; mt++)
                #pragma unroll
                for (int np = 0; np < 4; np++) {
                    mma16816(acc[mt][np * 2 + 0], aH[mt], bH[np] + 0);
                    mma16816(acc[mt][np * 2 + 1], aH[mt], bH[np] + 2);
                    mma16816(acc[mt][np * 2 + 0], aH[mt], bL[np] + 0);
                    mma16816(acc[mt][np * 2 + 1], aH[mt], bL[np] + 2);
                    mma16816(acc[mt][np * 2 + 0], aL[mt], bH[np] + 0);
                    mma16816(acc[mt][np * 2 + 1], aL[mt], bH[np] + 2);
                }
        }
        __syncthreads();

        #pragma unroll
        for (int mt = 0; mt < 2; mt++) {
            int rbase = row0 + mwarp * 32 + mt * 16 + (lane >> 2);
            #pragma unroll
            for (int nt = 0; nt < 8; nt++) {
                int colg = cb + nwarp * 64 + nt * 8 + (lane & 3) * 2;
                float2 b2 = *(const float2*)&g_qbias[colg];
                #pragma unroll
                for (int rh = 0; rh < 2; rh++) {
                    int row = rbase + rh * 8;
                    float2 o;
                    o.x = acc[mt][nt][rh * 2 + 0] + b2.x;
                    o.y = acc[mt][nt][rh * 2 + 1] + b2.y;
                    *(float2*)&g_qkv_all[(size_t)row * 384 + colg] = o;
                }
            }
        }
    }
}

// ---------------------------------------------------------------------------
// K3: softmax pooling per group. 1 block / group, 256 threads.
// ---------------------------------------------------------------------------
__global__ __launch_bounds__(256) void k3_pool(
    const int* __restrict__ sets,
    const float* __restrict__ aw, const float* __restrict__ ab)
{
    __shared__ float X[64][65];
    __shared__ float wgt[64];
    __shared__ int rows[64];
    __shared__ float wm[2], wsum[2];
    __shared__ float red[4][64];

    int t = threadIdx.x;
    int g = blockIdx.x;
    if (t < 64) rows[t] = sets[g * 64 + t];
    __syncthreads();
    {
        int l = t >> 2, c = (t & 3) * 16;
        const float* src = &g_inter_emb[(size_t)rows[l] * 64 + c];
        #pragma unroll
        for (int i = 0; i < 4; i++) {
            float4 v = *(const float4*)&src[i * 4];
            X[l][c + i * 4 + 0] = v.x;
            X[l][c + i * 4 + 1] = v.y;
            X[l][c + i * 4 + 2] = v.z;
            X[l][c + i * 4 + 3] = v.w;
        }
    }
    __syncthreads();

    float lg = 0.f, e = 0.f;
    if (t < 64) {
        lg = ab[0];
        #pragma unroll 8
        for (int k = 0; k < 64; k++) lg = fmaf(X[t][k], aw[k], lg);
        float m = lg;
        #pragma unroll
        for (int o = 16; o; o >>= 1) m = fmaxf(m, __shfl_xor_sync(0xffffffffu, m, o));
        if ((t & 31) == 0) wm[t >> 5] = m;
    }
    __syncthreads();
    if (t < 64) {
        float m = fmaxf(wm[0], wm[1]);
        e = expf(lg - m);
        float s = e;
        #pragma unroll
        for (int o = 16; o; o >>= 1) s += __shfl_xor_sync(0xffffffffu, s, o);
        if ((t & 31) == 0) wsum[t >> 5] = s;
    }
    __syncthreads();
    if (t < 64) wgt[t] = e / (wsum[0] + wsum[1]);
    __syncthreads();

    {
        int d = t & 63, seg = t >> 6;
        float acc = 0.f;
        #pragma unroll
        for (int k = seg * 16; k < seg * 16 + 16; k++)
            acc = fmaf(wgt[k], X[k][d], acc);
        red[seg][d] = acc;
    }
    __syncthreads();
    if (t < 64)
        g_pooled[g * 64 + t] = red[0][t] + red[1][t] + red[2][t] + red[3][t];
}

// ---------------------------------------------------------------------------
// K4a: inter QKV = pooled @ w_in^T + b.  grid (16, 2[mu/std]), 256 thr.
// ---------------------------------------------------------------------------
__global__ __launch_bounds__(256) void k4a_qkv(
    const float* __restrict__ wmi, const float* __restrict__ bmi,
    const float* __restrict__ wsi, const float* __restrict__ bsi)
{
    __shared__ float X[64][65];
    int t = threadIdx.x;
    int r0 = blockIdx.x * 64;
    int p = blockIdx.y;
    const float* Wi = p ? wsi : wmi;
    const float* bi = p ? bsi : bmi;

    {
        int l = t >> 2, c = (t & 3) * 16;
        #pragma unroll
        for (int i = 0; i < 4; i++) {
            float4 v = *(const float4*)&g_pooled[(r0 + l) * 64 + c + i * 4];
            X[l][c + i * 4 + 0] = v.x;
            X[l][c + i * 4 + 1] = v.y;
            X[l][c + i * 4 + 2] = v.z;
            X[l][c + i * 4 + 3] = v.w;
        }
    }
    __syncthreads();

    int l  = t & 63;
    int jb = t >> 6;
    for (int jj = 0; jj < 48; jj++) {
        int j = jb * 48 + jj;
        float acc = bi[j];
        #pragma unroll 8
        for (int k = 0; k < 64; k++) acc = fmaf(X[l][k], __ldg(&Wi[j * 64 + k]), acc);
        g_qkv[p][(r0 + l) * 192 + j] = acc;
    }
}

// ---------------------------------------------------------------------------
// K4b: inter attention (L=1024, dh=16). grid (16 qtiles, 4 heads, 2 passes),
// 512 threads: 8 key-chunks of 128 keys with partial online softmax + combine.
// ---------------------------------------------------------------------------
__global__ __launch_bounds__(512) void k4b_attn()
{
    extern __shared__ float sm4b[];
    float* Ks   = sm4b;
    float* Vs   = Ks + 1024 * 16;
    float* pm   = Vs + 1024 * 16;
    float* ps   = pm + 8 * 64;
    float* pacc = ps + 8 * 64;

    int t  = threadIdx.x;
    int kc = t >> 6, qi = t & 63;
    int q0 = blockIdx.x * 64;
    int h  = blockIdx.y;
    int p  = blockIdx.z;
    const float* QKV = g_qkv[p];

    for (int r = t; r < 1024; r += 512) {
        #pragma unroll
        for (int i = 0; i < 4; i++) {
            *(float4*)&Ks[r * 16 + i * 4] =
                *(const float4*)&QKV[(size_t)r * 192 + 64 + h * 16 + i * 4];
            *(float4*)&Vs[r * 16 + i * 4] =
                *(const float4*)&QKV[(size_t)r * 192 + 128 + h * 16 + i * 4];
        }
    }
    __syncthreads();

    float q[16];
    #pragma unroll
    for (int i = 0; i < 16; i++) q[i] = QKV[(size_t)(q0 + qi) * 192 + h * 16 + i];

    float m = -1e30f, ssum = 0.f, acc[16];
    #pragma unroll
    for (int i = 0; i < 16; i++) acc[i] = 0.f;

    int jbase = kc * 128;
    for (int j = jbase; j < jbase + 128; j++) {
        float s = 0.f;
        #pragma unroll
        for (int c = 0; c < 16; c++) s = fmaf(q[c], Ks[j * 16 + c], s);
        s *= 0.25f;
        float nm = fmaxf(m, s);
        float corr = expf(m - nm);
        float w = expf(s - nm);
        ssum = ssum * corr + w;
        #pragma unroll
        for (int c = 0; c < 16; c++) acc[c] = fmaf(acc[c], corr, w * Vs[j * 16 + c]);
        m = nm;
    }
    pm[kc * 64 + qi] = m;
    ps[kc * 64 + qi] = ssum;
    #pragma unroll
    for (int c = 0; c < 16; c++) pacc[(kc * 64 + qi) * 16 + c] = acc[c];
    __syncthreads();

    if (t < 64) {
        float gm = -1e30f;
        #pragma unroll
        for (int i = 0; i < 8; i++) gm = fmaxf(gm, pm[i * 64 + t]);
        float s = 0.f, o[16];
        #pragma unroll
        for (int c = 0; c < 16; c++) o[c] = 0.f;
        #pragma unroll
        for (int i = 0; i < 8; i++) {
            float w = expf(pm[i * 64 + t] - gm);
            s = fmaf(ps[i * 64 + t], w, s);
            #pragma unroll
            for (int c = 0; c < 16; c++)
                o[c] = fmaf(pacc[(i * 64 + t) * 16 + c], w, o[c]);
        }
        float inv = 1.f / s;
        #pragma unroll
        for (int c = 0; c < 16; c++)
            g_attno[p][(size_t)(q0 + t) * 64 + h * 16 + c] = o[c] * inv;
    }
}

// ---------------------------------------------------------------------------
// K4c: inter out-proj, softplus, sample. grid 16, 256 threads.
// ---------------------------------------------------------------------------
__global__ __launch_bounds__(256) void k4c_proj(
    const float* __restrict__ wmo, const float* __restrict__ bmo,
    const float* __restrict__ wso, const float* __restrict__ bso,
    const float* __restrict__ eps_inter)
{
    __shared__ float Om[64][65];
    __shared__ float Os[64][65];
    int t = threadIdx.x;
    int r0 = blockIdx.x * 64;
    {
        int l = t >> 2, c = (t & 3) * 16;
        for (int i = 0; i < 16; i++) {
            Om[l][c + i] = g_attno[0][(size_t)(r0 + l) * 64 + c + i];
            Os[l][c + i] = g_attno[1][(size_t)(r0 + l) * 64 + c + i];
        }
    }
    __syncthreads();

    int lb = t >> 4, db = t & 15;
    float am[4][4], as[4][4];
    #pragma unroll
    for (int i = 0; i < 4; i++)
        #pragma unroll
        for (int j = 0; j < 4; j++) { am[i][j] = 0.f; as[i][j] = 0.f; }

    #pragma unroll 4
    for (int k = 0; k < 64; k++) {
        float om[4], os[4], wmv[4], wsv[4];
        #pragma unroll
        for (int i = 0; i < 4; i++) { om[i] = Om[lb * 4 + i][k]; os[i] = Os[lb * 4 + i][k]; }
        #pragma unroll
        for (int j = 0; j < 4; j++) {
            wmv[j] = __ldg(&wmo[(db * 4 + j) * 64 + k]);
            wsv[j] = __ldg(&wso[(db * 4 + j) * 64 + k]);
        }
        #pragma unroll
        for (int i = 0; i < 4; i++)
            #pragma unroll
            for (int j = 0; j < 4; j++) {
                am[i][j] = fmaf(om[i], wmv[j], am[i][j]);
                as[i][j] = fmaf(os[i], wsv[j], as[i][j]);
            }
    }
    #pragma unroll
    for (int i = 0; i < 4; i++) {
        int gi = r0 + lb * 4 + i;
        #pragma unroll
        for (int j = 0; j < 4; j++) {
            int d = db * 4 + j;
            float mu  = am[i][j] + bmo[d];
            float st  = softplusf(as[i][j] + bso[d] - 5.f);
            g_inter_mu[gi * 64 + d] = mu;
            g_inter_std[gi * 64 + d] = st;
            g_inter_sample[gi * 64 + d] = fmaf(st, eps_inter[gi * 64 + d], mu);
        }
    }
}

// ---------------------------------------------------------------------------
// K2: intra attention per group (QKV precomputed by k2a), out-proj,
// fused with ALL final scatter writes. 1 block / group, 256 threads, ~100KB smem.
// ---------------------------------------------------------------------------
__global__ __launch_bounds__(256) void k2_intra(
    const int* __restrict__ sets,
    const float* __restrict__ wmo, const float* __restrict__ bmo,
    const float* __restrict__ wso, const float* __restrict__ bso,
    const float* __restrict__ eps_intra,
    float* __restrict__ out_ac, float* __restrict__ out_mu, float* __restrict__ out_std)
{
    extern __shared__ float sm[];
    float* QKV  = sm;                  // [64][196]
    float* O    = QKV + 64 * 196;      // [64][65]
    float* Wo   = O + 64 * 65;         // [64][65]
    float* bout = Wo + 64 * 65;        // [64]
    float* MUb  = bout + 64;           // [64][64]
    int*   rows = (int*)(MUb + 64 * 64); // [64]

    int t = threadIdx.x;
    int g = blockIdx.x;
    if (t < 64) rows[t] = sets[g * 64 + t];
    __syncthreads();

    for (int p = 0; p < 2; p++) {
        const float* wOut = p ? wso : wmo;
        const float* bOut = p ? bso : bmo;
        __syncthreads();
        // load out-proj weights
        for (int v = t; v < 1024; v += 256) {
            int j = v >> 4; int cv = (v & 15) * 4;
            float4 w4 = *(const float4*)&wOut[j * 64 + cv];
            Wo[j * 65 + cv + 0] = w4.x; Wo[j * 65 + cv + 1] = w4.y;
            Wo[j * 65 + cv + 2] = w4.z; Wo[j * 65 + cv + 3] = w4.w;
        }
        if (t < 64) bout[t] = bOut[t];
        // gather QKV rows for this group's 64 agents (bias already included)
        {
            int l = t >> 2, q4 = t & 3;
            const float* src = &g_qkv_all[(size_t)rows[l] * 384 + p * 192 + q4 * 48];
            float* dst = &QKV[l * 196 + q4 * 48];
            #pragma unroll
            for (int i = 0; i < 12; i++)
                *(float4*)&dst[i * 4] = *(const float4*)&src[i * 4];
        }
        __syncthreads();

        // attention: thread = (query i, head h), online softmax
        {
            int i = t & 63, h = t >> 6;
            float q[16];
            #pragma unroll
            for (int c = 0; c < 16; c++) q[c] = QKV[i * 196 + h * 16 + c];
            float m = -1e30f, ssum = 0.f, acc[16];
            #pragma unroll
            for (int c = 0; c < 16; c++) acc[c] = 0.f;
            for (int j = 0; j < 64; j++) {
                float s = 0.f;
                #pragma unroll
                for (int c = 0; c < 16; c++) s = fmaf(q[c], QKV[j * 196 + 64 + h * 16 + c], s);
                s *= 0.25f;
                float nm = fmaxf(m, s);
                float corr = expf(m - nm);
                float w = expf(s - nm);
                ssum = ssum * corr + w;
                #pragma unroll
                for (int c = 0; c < 16; c++)
                    acc[c] = fmaf(acc[c], corr, w * QKV[j * 196 + 128 + h * 16 + c]);
                m = nm;
            }
            float inv = 1.f / ssum;
            #pragma unroll
            for (int c = 0; c < 16; c++) O[i * 65 + h * 16 + c] = acc[c] * inv;
        }
        __syncthreads();

        // out proj (thread: 4 rows x 4 cols) + fused epilogue / global writes
        {
            int lb = t >> 4, db = t & 15;
            float acc[4][4];
            #pragma unroll
            for (int i = 0; i < 4; i++)
                #pragma unroll
                for (int j = 0; j < 4; j++) acc[i][j] = 0.f;
            #pragma unroll 4
            for (int k = 0; k < 64; k++) {
                float ov[4], wv[4];
                #pragma unroll
                for (int i = 0; i < 4; i++) ov[i] = O[(lb * 4 + i) * 65 + k];
                #pragma unroll
                for (int j = 0; j < 4; j++) wv[j] = Wo[(db * 4 + j) * 65 + k];
                #pragma unroll
                for (int i = 0; i < 4; i++)
                    #pragma unroll
                    for (int j = 0; j < 4; j++)
                        acc[i][j] = fmaf(ov[i], wv[j], acc[i][j]);
            }
            int d0 = db * 4;
            #pragma unroll
            for (int i = 0; i < 4; i++) {
                int l = lb * 4 + i;
                int row = rows[l];
                float4 v;
                v.x = acc[i][0] + bout[d0 + 0];
                v.y = acc[i][1] + bout[d0 + 1];
                v.z = acc[i][2] + bout[d0 + 2];
                v.w = acc[i][3] + bout[d0 + 3];
                if (p == 0) {
                    *(float4*)&MUb[l * 64 + d0] = v;
                    *(float4*)&out_mu[(size_t)row * 128 + d0] = v;
                    *(float4*)&out_mu[(size_t)row * 128 + 64 + d0] =
                        *(const float4*)&g_inter_mu[g * 64 + d0];
                    *(float4*)&out_ac[(size_t)row * 640 + 512 + d0] =
                        *(const float4*)&g_inter_sample[g * 64 + d0];
                } else {
                    float4 st;
                    st.x = softplusf(v.x - 5.f);
                    st.y = softplusf(v.y - 5.f);
                    st.z = softplusf(v.z - 5.f);
                    st.w = softplusf(v.w - 5.f);
                    float4 mu4 = *(const float4*)&MUb[l * 64 + d0];
                    float4 ep  = *(const float4*)&eps_intra[(size_t)row * 64 + d0];
                    float4 samp;
                    samp.x = fmaf(st.x, ep.x, mu4.x);
                    samp.y = fmaf(st.y, ep.y, mu4.y);
                    samp.z = fmaf(st.z, ep.z, mu4.z);
                    samp.w = fmaf(st.w, ep.w, mu4.w);
                    *(float4*)&out_std[(size_t)row * 128 + d0] = st;
                    *(float4*)&out_std[(size_t)row * 128 + 64 + d0] =
                        *(const float4*)&g_inter_std[g * 64 + d0];
                    *(float4*)&out_ac[(size_t)row * 640 + 576 + d0] = samp;
                }
            }
        }
    }
}

// ---------------------------------------------------------------------------
extern "C" void kernel_launch(void* const* d_in, const int* in_sizes, int n_in,
                              void* d_out, int out_size)
{
    (void)in_sizes; (void)n_in; (void)out_size;
    const float* obs        = (const float*)d_in[0];
    const int*   sets       = (const int*)  d_in[1];
    const float* eps_intra  = (const float*)d_in[2];
    const float* eps_inter  = (const float*)d_in[3];
    const float* local_w    = (const float*)d_in[4];
    const float* local_b    = (const float*)d_in[5];
    const float* inter_emb_w= (const float*)d_in[6];
    const float* inter_emb_b= (const float*)d_in[7];
    const float* intra_emb_w= (const float*)d_in[8];
    const float* intra_emb_b= (const float*)d_in[9];
    const float* amu_in_w   = (const float*)d_in[10];
    const float* amu_in_b   = (const float*)d_in[11];
    const float* amu_out_w  = (const float*)d_in[12];
    const float* amu_out_b  = (const float*)d_in[13];
    const float* astd_in_w  = (const float*)d_in[14];
    const float* astd_in_b  = (const float*)d_in[15];
    const float* astd_out_w = (const float*)d_in[16];
    const float* astd_out_b = (const float*)d_in[17];
    const float* emu_in_w   = (const float*)d_in[18];
    const float* emu_in_b   = (const float*)d_in[19];
    const float* emu_out_w  = (const float*)d_in[20];
    const float* emu_out_b  = (const float*)d_in[21];
    const float* estd_in_w  = (const float*)d_in[22];
    const float* estd_in_b  = (const float*)d_in[23];
    const float* estd_out_w = (const float*)d_in[24];
    const float* estd_out_b = (const float*)d_in[25];
    const float* attset_w   = (const float*)d_in[26];
    const float* attset_b   = (const float*)d_in[27];

    float* out_ac  = (float*)d_out;
    float* out_mu  = out_ac + (size_t)NN * 640;
    float* out_std = out_mu + (size_t)NN * 128;

    const int k2_smem  = (64*196 + 64*65 + 64*65 + 64 + 64*64) * 4 + 64 * 4;
    const int k4b_smem = (2 * 1024 * 16 + 8 * 64 * 2 + 8 * 64 * 16) * 4;
    cudaFuncSetAttribute(k2_intra, cudaFuncAttributeMaxDynamicSharedMemorySize, k2_smem);
    cudaFuncSetAttribute(k4b_attn, cudaFuncAttributeMaxDynamicSharedMemorySize, k4b_smem);
    cudaFuncSetAttribute(k1_mma, cudaFuncAttributeMaxDynamicSharedMemorySize, K1_SMEM);
    cudaFuncSetAttribute(k2a_qkv_gemm, cudaFuncAttributeMaxDynamicSharedMemorySize, K2A_SMEM);

    // split inputs into bf16 hi/lo
    k0_split_A<<<(NN * OBSD / 4 + 255) / 256, 256>>>((const float4*)obs);
    k0_split_W<<<640, 256>>>(local_w, local_b, inter_emb_w, inter_emb_b,
                             intra_emb_w, intra_emb_b);
    k0_split_Wq<<<384, 64>>>(amu_in_w, amu_in_b, astd_in_w, astd_in_b);

    k1_mma<<<512, 256, K1_SMEM>>>(out_ac);
    k2a_qkv_gemm<<<512, 256, K2A_SMEM>>>();

    k3_pool<<<GG, 256>>>(sets, attset_w, attset_b);
    dim3 g4a(16, 2);
    k4a_qkv<<<g4a, 256>>>(emu_in_w, emu_in_b, estd_in_w, estd_in_b);
    dim3 g4b(16, 4, 2);
    k4b_attn<<<g4b, 512, k4b_smem>>>();
    k4c_proj<<<16, 256>>>(emu_out_w, emu_out_b, estd_out_w, estd_out_b, eps_inter);
    k2_intra<<<GG, 256, k2_smem>>>(sets,
                                   amu_out_w, amu_out_b, astd_out_w, astd_out_b,
                                   eps_intra, out_ac, out_mu, out_std);
}

// round 11
// speedup vs baseline: 2.7246x; 1.1561x over previous
#include <cuda_runtime.h>
#include <cuda_bf16.h>
#include <math.h>
#include <stdint.h>

#define NN 65536
#define GG 1024
#define SSZ 64
#define DD 64
#define OBSD 256
#define HIDD 512

// ---------------- scratch (device globals; no allocations allowed) ----------
__device__ __align__(16) float g_inter_emb[NN * DD];
__device__ __align__(16) float g_pooled[GG * DD];
__device__ __align__(16) float g_qkv[2][GG * 3 * DD];
__device__ __align__(16) float g_attno[2][GG * DD];
__device__ __align__(16) float g_inter_mu[GG * DD];
__device__ __align__(16) float g_inter_std[GG * DD];
__device__ __align__(16) float g_inter_sample[GG * DD];

// bf16 hi/lo split operands
__device__ __align__(16) __nv_bfloat16 g_Ah[(size_t)NN * OBSD];
__device__ __align__(16) __nv_bfloat16 g_Al[(size_t)NN * OBSD];
__device__ __align__(16) __nv_bfloat16 g_Wh[640 * OBSD];
__device__ __align__(16) __nv_bfloat16 g_Wl[640 * OBSD];
__device__ float g_bias[640];

// intra_emb as bf16 hi/lo (input to k2a GEMM)
__device__ __align__(16) __nv_bfloat16 g_Eh[(size_t)NN * DD];
__device__ __align__(16) __nv_bfloat16 g_El[(size_t)NN * DD];
// packed intra in-proj weights [384=192mu+192std][64] hi/lo + bias
__device__ __align__(16) __nv_bfloat16 g_Wqh[384 * DD];
__device__ __align__(16) __nv_bfloat16 g_Wql[384 * DD];
__device__ float g_qbias[384];
// QKV (bias included) for all agents: [65536][384] (0..191 mu, 192..383 std)
__device__ __align__(16) float g_qkv_all[(size_t)NN * 384];

__device__ __forceinline__ float softplusf(float x) {
    return (x > 20.f) ? x : __logf(1.f + __expf(x));
}
__device__ __forceinline__ float ftanh(float x) {
    float ax = fabsf(x);
    float t = __expf(-2.f * ax);
    float r = __fdividef(1.f - t, 1.f + t);
    return copysignf(r, x);
}

__device__ __forceinline__ uint32_t smem_u32(const void* p) {
    uint32_t a;
    asm("{ .reg .u64 t; cvta.to.shared.u64 t, %1; cvt.u32.u64 %0, t; }" : "=r"(a) : "l"(p));
    return a;
}
__device__ __forceinline__ uint32_t swz128(uint32_t off) {
    return off ^ ((off >> 3) & 0x70);
}
__device__ __forceinline__ void ldm_x4(uint32_t* r, uint32_t addr) {
    asm volatile("ldmatrix.sync.aligned.m8n8.x4.shared.b16 {%0,%1,%2,%3}, [%4];"
        : "=r"(r[0]), "=r"(r[1]), "=r"(r[2]), "=r"(r[3]) : "r"(addr));
}
__device__ __forceinline__ void mma16816(float* d, const uint32_t* a, const uint32_t* b) {
    asm volatile(
        "mma.sync.aligned.m16n8k16.row.col.f32.bf16.bf16.f32 "
        "{%0,%1,%2,%3}, {%4,%5,%6,%7}, {%8,%9}, {%0,%1,%2,%3};"
        : "+f"(d[0]), "+f"(d[1]), "+f"(d[2]), "+f"(d[3])
        : "r"(a[0]), "r"(a[1]), "r"(a[2]), "r"(a[3]), "r"(b[0]), "r"(b[1]));
}
__device__ __forceinline__ void cpasync16(uint32_t dst, const void* src) {
    asm volatile("cp.async.cg.shared.global [%0], [%1], 16;" :: "r"(dst), "l"(src));
}
#define CP_COMMIT() asm volatile("cp.async.commit_group;" ::: "memory")
#define CP_WAIT1()  asm volatile("cp.async.wait_group 1;" ::: "memory")
#define CP_WAIT0()  asm volatile("cp.async.wait_group 0;" ::: "memory")

// ---------------------------------------------------------------------------
// K0a: split obs fp32 -> bf16 hi/lo
// ---------------------------------------------------------------------------
__global__ __launch_bounds__(256) void k0_split_A(const float4* __restrict__ obs4) {
    size_t i = (size_t)blockIdx.x * 256 + threadIdx.x;
    float4 v = obs4[i];
    size_t b = i * 4;
    __nv_bfloat16 h0 = __float2bfloat16(v.x);
    __nv_bfloat16 h1 = __float2bfloat16(v.y);
    __nv_bfloat16 h2 = __float2bfloat16(v.z);
    __nv_bfloat16 h3 = __float2bfloat16(v.w);
    __nv_bfloat16 l0 = __float2bfloat16(v.x - __bfloat162float(h0));
    __nv_bfloat16 l1 = __float2bfloat16(v.y - __bfloat162float(h1));
    __nv_bfloat16 l2 = __float2bfloat16(v.z - __bfloat162float(h2));
    __nv_bfloat16 l3 = __float2bfloat16(v.w - __bfloat162float(h3));
    *(__nv_bfloat162*)&g_Ah[b]     = __halves2bfloat162(h0, h1);
    *(__nv_bfloat162*)&g_Ah[b + 2] = __halves2bfloat162(h2, h3);
    *(__nv_bfloat162*)&g_Al[b]     = __halves2bfloat162(l0, l1);
    *(__nv_bfloat162*)&g_Al[b + 2] = __halves2bfloat162(l2, l3);
}

// K0b: pack embed weights [640][256] = [local(512); inter(64); intra(64)] + bias
__global__ __launch_bounds__(256) void k0_split_W(
    const float* __restrict__ lw, const float* __restrict__ lb,
    const float* __restrict__ iw, const float* __restrict__ ib,
    const float* __restrict__ tw, const float* __restrict__ tb)
{
    int row = blockIdx.x, col = threadIdx.x;
    const float* src; const float* bs; int r;
    if (row < 512)      { src = lw; bs = lb; r = row; }
    else if (row < 576) { src = iw; bs = ib; r = row - 512; }
    else                { src = tw; bs = tb; r = row - 576; }
    float x = src[r * OBSD + col];
    __nv_bfloat16 h = __float2bfloat16(x);
    g_Wh[row * OBSD + col] = h;
    g_Wl[row * OBSD + col] = __float2bfloat16(x - __bfloat162float(h));
    if (col == 0) g_bias[row] = bs[r];
}

// K0c: pack intra in-proj weights [384][64] (mu 0..191, std 192..383) + bias
__global__ __launch_bounds__(64) void k0_split_Wq(
    const float* __restrict__ wmi, const float* __restrict__ bmi,
    const float* __restrict__ wsi, const float* __restrict__ bsi)
{
    int row = blockIdx.x, col = threadIdx.x;
    const float* src; const float* bs; int r;
    if (row < 192) { src = wmi; bs = bmi; r = row; }
    else           { src = wsi; bs = bsi; r = row - 192; }
    float x = src[r * 64 + col];
    __nv_bfloat16 h = __float2bfloat16(x);
    g_Wqh[row * 64 + col] = h;
    g_Wql[row * 64 + col] = __float2bfloat16(x - __bfloat162float(h));
    if (col == 0) g_qbias[row] = bs[r];
}

// ---------------------------------------------------------------------------
// K1: mma.sync bf16-split GEMM  C[65536,640] = tanh(A @ W^T + b).
// grid (512, 10), block 256 (8 warps = 4M x 2N), launch_bounds(256,2).
// Tile M=128, N=64. K chunks of 64, cp.async double-buffered.
// nb 0..7 -> out_ac, nb==8 -> g_inter_emb fp32, nb==9 -> g_Eh/g_El bf16 split.
// ---------------------------------------------------------------------------
#define K1_AH 0
#define K1_AL 16384
#define K1_BH 32768
#define K1_BL 40960
#define K1_BUF 49152
#define K1_SMEM (2 * K1_BUF)

__global__ __launch_bounds__(256, 2) void k1_mma(float* __restrict__ out_ac)
{
    extern __shared__ char sm1[];
    uint32_t smb = smem_u32(sm1);
    int t = threadIdx.x;
    int lane = t & 31, wid = t >> 5;
    int mwarp = wid & 3, nwarp = wid >> 2;
    int row0 = blockIdx.x * 128;
    int nb = blockIdx.y;
    int cb = nb * 64;

    int arow = t >> 1, akseg = t & 1;     // A: 128 rows x 2 halves
    int brow = t >> 2, bkseg = t & 3;     // B: 64 rows x 4 quarters

    uint32_t a_row_im = (uint32_t)(mwarp * 32 + (lane & 15));
    uint32_t a_kb_im  = (uint32_t)((lane >> 4) * 16);
    uint32_t b_row_im = (uint32_t)(nwarp * 32 + ((lane >> 4) & 1) * 8 + (lane & 7));
    uint32_t b_kb_im  = (uint32_t)(((lane >> 3) & 1) * 16);

    auto stage = [&](int buf, int ck) {
        int k0 = ck * 64;
        uint32_t base = smb + buf * K1_BUF;
        size_t aoff = (size_t)(row0 + arow) * OBSD + k0 + akseg * 32;
        #pragma unroll
        for (int i = 0; i < 4; i++) {
            uint32_t so = swz128((uint32_t)arow * 128 + akseg * 64 + i * 16);
            cpasync16(base + K1_AH + so, &g_Ah[aoff + i * 8]);
            cpasync16(base + K1_AL + so, &g_Al[aoff + i * 8]);
        }
        size_t boff = (size_t)(cb + brow) * OBSD + k0 + bkseg * 16;
        #pragma unroll
        for (int i = 0; i < 2; i++) {
            uint32_t so = swz128((uint32_t)brow * 128 + bkseg * 32 + i * 16);
            cpasync16(base + K1_BH + so, &g_Wh[boff + i * 8]);
            cpasync16(base + K1_BL + so, &g_Wl[boff + i * 8]);
        }
    };

    float acc[2][4][4];
    #pragma unroll
    for (int mt = 0; mt < 2; mt++)
        #pragma unroll
        for (int nt = 0; nt < 4; nt++)
            #pragma unroll
            for (int e = 0; e < 4; e++) acc[mt][nt][e] = 0.f;

    stage(0, 0);
    CP_COMMIT();

    for (int ck = 0; ck < 4; ck++) {
        int buf = ck & 1;
        if (ck + 1 < 4) {
            stage(buf ^ 1, ck + 1);
            CP_COMMIT();
            CP_WAIT1();
        } else {
            CP_WAIT0();
        }
        __syncthreads();

        uint32_t base = smb + buf * K1_BUF;
        #pragma unroll
        for (int ks = 0; ks < 4; ks++) {
            uint32_t aH[2][4], aL[2][4];
            #pragma unroll
            for (int mt = 0; mt < 2; mt++) {
                uint32_t off = swz128((a_row_im + mt * 16) * 128 + ks * 32 + a_kb_im);
                ldm_x4(aH[mt], base + K1_AH + off);
                ldm_x4(aL[mt], base + K1_AL + off);
            }
            uint32_t bH[2][4], bL[2][4];
            #pragma unroll
            for (int np = 0; np < 2; np++) {
                uint32_t off = swz128((b_row_im + np * 16) * 128 + ks * 32 + b_kb_im);
                ldm_x4(bH[np], base + K1_BH + off);
                ldm_x4(bL[np], base + K1_BL + off);
            }
            #pragma unroll
            for (int mt = 0; mt < 2; mt++)
                #pragma unroll
                for (int np = 0; np < 2; np++) {
                    mma16816(acc[mt][np * 2 + 0], aH[mt], bH[np] + 0);
                    mma16816(acc[mt][np * 2 + 1], aH[mt], bH[np] + 2);
                    mma16816(acc[mt][np * 2 + 0], aH[mt], bL[np] + 0);
                    mma16816(acc[mt][np * 2 + 1], aH[mt], bL[np] + 2);
                    mma16816(acc[mt][np * 2 + 0], aL[mt], bH[np] + 0);
                    mma16816(acc[mt][np * 2 + 1], aL[mt], bH[np] + 2);
                }
        }
        __syncthreads();
    }

    // epilogue: bias + tanh
    #pragma unroll
    for (int mt = 0; mt < 2; mt++) {
        int rbase = row0 + mwarp * 32 + mt * 16 + (lane >> 2);
        #pragma unroll
        for (int nt = 0; nt < 4; nt++) {
            int colT = nwarp * 32 + nt * 8 + (lane & 3) * 2;
            float2 b2 = *(const float2*)&g_bias[cb + colT];
            #pragma unroll
            for (int rh = 0; rh < 2; rh++) {
                int row = rbase + rh * 8;
                float2 o;
                o.x = ftanh(acc[mt][nt][rh * 2 + 0] + b2.x);
                o.y = ftanh(acc[mt][nt][rh * 2 + 1] + b2.y);
                if (nb < 8) {
                    *(float2*)&out_ac[(size_t)row * 640 + cb + colT] = o;
                } else if (nb == 8) {
                    *(float2*)&g_inter_emb[(size_t)row * 64 + colT] = o;
                } else {
                    __nv_bfloat16 h0 = __float2bfloat16(o.x);
                    __nv_bfloat16 h1 = __float2bfloat16(o.y);
                    __nv_bfloat16 l0 = __float2bfloat16(o.x - __bfloat162float(h0));
                    __nv_bfloat16 l1 = __float2bfloat16(o.y - __bfloat162float(h1));
                    *(__nv_bfloat162*)&g_Eh[(size_t)row * 64 + colT] = __halves2bfloat162(h0, h1);
                    *(__nv_bfloat162*)&g_El[(size_t)row * 64 + colT] = __halves2bfloat162(l0, l1);
                }
            }
        }
    }
}

// ---------------------------------------------------------------------------
// K2a: mma.sync bf16-split GEMM  QKV_all[65536,384] = E @ Wq^T + qbias.
// grid (512, 6), block 256 (8 warps = 4M x 2N), launch_bounds(256,2).
// Tile M=128, N=64, K=64 (single chunk).
// ---------------------------------------------------------------------------
#define K2A_AH 0
#define K2A_AL 16384
#define K2A_BH 32768
#define K2A_BL 40960
#define K2A_SMEM 49152

__global__ __launch_bounds__(256, 2) void k2a_qkv_gemm()
{
    extern __shared__ char sm2[];
    uint32_t smb = smem_u32(sm2);
    int t = threadIdx.x;
    int lane = t & 31, wid = t >> 5;
    int mwarp = wid & 3, nwarp = wid >> 2;
    int row0 = blockIdx.x * 128;
    int cb = blockIdx.y * 64;

    uint32_t a_row_im = (uint32_t)(mwarp * 32 + (lane & 15));
    uint32_t a_kb_im  = (uint32_t)((lane >> 4) * 16);
    uint32_t b_row_im = (uint32_t)(nwarp * 32 + ((lane >> 4) & 1) * 8 + (lane & 7));
    uint32_t b_kb_im  = (uint32_t)(((lane >> 3) & 1) * 16);

    {
        int arow = t >> 1, akseg = t & 1;
        size_t aoff = (size_t)(row0 + arow) * 64 + akseg * 32;
        #pragma unroll
        for (int i = 0; i < 4; i++) {
            uint32_t so = swz128((uint32_t)arow * 128 + akseg * 64 + i * 16);
            cpasync16(smb + K2A_AH + so, &g_Eh[aoff + i * 8]);
            cpasync16(smb + K2A_AL + so, &g_El[aoff + i * 8]);
        }
        int brow = t >> 2, bkseg = t & 3;
        size_t boff = (size_t)(cb + brow) * 64 + bkseg * 16;
        #pragma unroll
        for (int i = 0; i < 2; i++) {
            uint32_t so = swz128((uint32_t)brow * 128 + bkseg * 32 + i * 16);
            cpasync16(smb + K2A_BH + so, &g_Wqh[boff + i * 8]);
            cpasync16(smb + K2A_BL + so, &g_Wql[boff + i * 8]);
        }
    }
    CP_COMMIT();
    CP_WAIT0();
    __syncthreads();

    float acc[2][4][4];
    #pragma unroll
    for (int mt = 0; mt < 2; mt++)
        #pragma unroll
        for (int nt = 0; nt < 4; nt++)
            #pragma unroll
            for (int e = 0; e < 4; e++) acc[mt][nt][e] = 0.f;

    #pragma unroll
    for (int ks = 0; ks < 4; ks++) {
        uint32_t aH[2][4], aL[2][4];
        #pragma unroll
        for (int mt = 0; mt < 2; mt++) {
            uint32_t off = swz128((a_row_im + mt * 16) * 128 + ks * 32 + a_kb_im);
            ldm_x4(aH[mt], smb + K2A_AH + off);
            ldm_x4(aL[mt], smb + K2A_AL + off);
        }
        uint32_t bH[2][4], bL[2][4];
        #pragma unroll
        for (int np = 0; np < 2; np++) {
            uint32_t off = swz128((b_row_im + np * 16) * 128 + ks * 32 + b_kb_im);
            ldm_x4(bH[np], smb + K2A_BH + off);
            ldm_x4(bL[np], smb + K2A_BL + off);
        }
        #pragma unroll
        for (int mt = 0; mt < 2; mt++)
            #pragma unroll
            for (int np = 0; np < 2; np++) {
                mma16816(acc[mt][np * 2 + 0], aH[mt], bH[np] + 0);
                mma16816(acc[mt][np * 2 + 1], aH[mt], bH[np] + 2);
                mma16816(acc[mt][np * 2 + 0], aH[mt], bL[np] + 0);
                mma16816(acc[mt][np * 2 + 1], aH[mt], bL[np] + 2);
                mma16816(acc[mt][np * 2 + 0], aL[mt], bH[np] + 0);
                mma16816(acc[mt][np * 2 + 1], aL[mt], bH[np] + 2);
            }
    }

    #pragma unroll
    for (int mt = 0; mt < 2; mt++) {
        int rbase = row0 + mwarp * 32 + mt * 16 + (lane >> 2);
        #pragma unroll
        for (int nt = 0; nt < 4; nt++) {
            int colg = cb + nwarp * 32 + nt * 8 + (lane & 3) * 2;
            float2 b2 = *(const float2*)&g_qbias[colg];
            #pragma unroll
            for (int rh = 0; rh < 2; rh++) {
                int row = rbase + rh * 8;
                float2 o;
                o.x = acc[mt][nt][rh * 2 + 0] + b2.x;
                o.y = acc[mt][nt][rh * 2 + 1] + b2.y;
                *(float2*)&g_qkv_all[(size_t)row * 384 + colg] = o;
            }
        }
    }
}

// ---------------------------------------------------------------------------
// K3: softmax pooling per group. 1 block / group, 256 threads.
// ---------------------------------------------------------------------------
__global__ __launch_bounds__(256) void k3_pool(
    const int* __restrict__ sets,
    const float* __restrict__ aw, const float* __restrict__ ab)
{
    __shared__ float X[64][65];
    __shared__ float wgt[64];
    __shared__ int rows[64];
    __shared__ float wm[2], wsum[2];
    __shared__ float red[4][64];

    int t = threadIdx.x;
    int g = blockIdx.x;
    if (t < 64) rows[t] = sets[g * 64 + t];
    __syncthreads();
    {
        int l = t >> 2, c = (t & 3) * 16;
        const float* src = &g_inter_emb[(size_t)rows[l] * 64 + c];
        #pragma unroll
        for (int i = 0; i < 4; i++) {
            float4 v = *(const float4*)&src[i * 4];
            X[l][c + i * 4 + 0] = v.x;
            X[l][c + i * 4 + 1] = v.y;
            X[l][c + i * 4 + 2] = v.z;
            X[l][c + i * 4 + 3] = v.w;
        }
    }
    __syncthreads();

    float lg = 0.f, e = 0.f;
    if (t < 64) {
        lg = ab[0];
        #pragma unroll 8
        for (int k = 0; k < 64; k++) lg = fmaf(X[t][k], aw[k], lg);
        float m = lg;
        #pragma unroll
        for (int o = 16; o; o >>= 1) m = fmaxf(m, __shfl_xor_sync(0xffffffffu, m, o));
        if ((t & 31) == 0) wm[t >> 5] = m;
    }
    __syncthreads();
    if (t < 64) {
        float m = fmaxf(wm[0], wm[1]);
        e = __expf(lg - m);
        float s = e;
        #pragma unroll
        for (int o = 16; o; o >>= 1) s += __shfl_xor_sync(0xffffffffu, s, o);
        if ((t & 31) == 0) wsum[t >> 5] = s;
    }
    __syncthreads();
    if (t < 64) wgt[t] = e / (wsum[0] + wsum[1]);
    __syncthreads();

    {
        int d = t & 63, seg = t >> 6;
        float acc = 0.f;
        #pragma unroll
        for (int k = seg * 16; k < seg * 16 + 16; k++)
            acc = fmaf(wgt[k], X[k][d], acc);
        red[seg][d] = acc;
    }
    __syncthreads();
    if (t < 64)
        g_pooled[g * 64 + t] = red[0][t] + red[1][t] + red[2][t] + red[3][t];
}

// ---------------------------------------------------------------------------
// K4a: inter QKV = pooled @ w_in^T + b.  grid (16, 2[mu/std]), 256 thr.
// ---------------------------------------------------------------------------
__global__ __launch_bounds__(256) void k4a_qkv(
    const float* __restrict__ wmi, const float* __restrict__ bmi,
    const float* __restrict__ wsi, const float* __restrict__ bsi)
{
    __shared__ float X[64][65];
    int t = threadIdx.x;
    int r0 = blockIdx.x * 64;
    int p = blockIdx.y;
    const float* Wi = p ? wsi : wmi;
    const float* bi = p ? bsi : bmi;

    {
        int l = t >> 2, c = (t & 3) * 16;
        #pragma unroll
        for (int i = 0; i < 4; i++) {
            float4 v = *(const float4*)&g_pooled[(r0 + l) * 64 + c + i * 4];
            X[l][c + i * 4 + 0] = v.x;
            X[l][c + i * 4 + 1] = v.y;
            X[l][c + i * 4 + 2] = v.z;
            X[l][c + i * 4 + 3] = v.w;
        }
    }
    __syncthreads();

    int l  = t & 63;
    int jb = t >> 6;
    for (int jj = 0; jj < 48; jj++) {
        int j = jb * 48 + jj;
        float acc = bi[j];
        #pragma unroll 8
        for (int k = 0; k < 64; k++) acc = fmaf(X[l][k], __ldg(&Wi[j * 64 + k]), acc);
        g_qkv[p][(r0 + l) * 192 + j] = acc;
    }
}

// ---------------------------------------------------------------------------
// K4b: inter attention (L=1024, dh=16). grid (16 qtiles, 4 heads, 2 passes),
// 512 threads: 8 key-chunks of 128 keys with partial online softmax + combine.
// ---------------------------------------------------------------------------
__global__ __launch_bounds__(512) void k4b_attn()
{
    extern __shared__ float sm4b[];
    float* Ks   = sm4b;
    float* Vs   = Ks + 1024 * 16;
    float* pm   = Vs + 1024 * 16;
    float* ps   = pm + 8 * 64;
    float* pacc = ps + 8 * 64;

    int t  = threadIdx.x;
    int kc = t >> 6, qi = t & 63;
    int q0 = blockIdx.x * 64;
    int h  = blockIdx.y;
    int p  = blockIdx.z;
    const float* QKV = g_qkv[p];

    for (int r = t; r < 1024; r += 512) {
        #pragma unroll
        for (int i = 0; i < 4; i++) {
            *(float4*)&Ks[r * 16 + i * 4] =
                *(const float4*)&QKV[(size_t)r * 192 + 64 + h * 16 + i * 4];
            *(float4*)&Vs[r * 16 + i * 4] =
                *(const float4*)&QKV[(size_t)r * 192 + 128 + h * 16 + i * 4];
        }
    }
    __syncthreads();

    float q[16];
    #pragma unroll
    for (int i = 0; i < 16; i++) q[i] = QKV[(size_t)(q0 + qi) * 192 + h * 16 + i];

    float m = -1e30f, ssum = 0.f, acc[16];
    #pragma unroll
    for (int i = 0; i < 16; i++) acc[i] = 0.f;

    int jbase = kc * 128;
    for (int j = jbase; j < jbase + 128; j++) {
        float s = 0.f;
        #pragma unroll
        for (int c = 0; c < 16; c++) s = fmaf(q[c], Ks[j * 16 + c], s);
        s *= 0.25f;
        if (s <= m) {
            float w = __expf(s - m);
            ssum += w;
            #pragma unroll
            for (int c = 0; c < 16; c++) acc[c] = fmaf(w, Vs[j * 16 + c], acc[c]);
        } else {
            float corr = __expf(m - s);
            ssum = fmaf(ssum, corr, 1.f);
            #pragma unroll
            for (int c = 0; c < 16; c++) acc[c] = fmaf(acc[c], corr, Vs[j * 16 + c]);
            m = s;
        }
    }
    pm[kc * 64 + qi] = m;
    ps[kc * 64 + qi] = ssum;
    #pragma unroll
    for (int c = 0; c < 16; c++) pacc[(kc * 64 + qi) * 16 + c] = acc[c];
    __syncthreads();

    if (t < 64) {
        float gm = -1e30f;
        #pragma unroll
        for (int i = 0; i < 8; i++) gm = fmaxf(gm, pm[i * 64 + t]);
        float s = 0.f, o[16];
        #pragma unroll
        for (int c = 0; c < 16; c++) o[c] = 0.f;
        #pragma unroll
        for (int i = 0; i < 8; i++) {
            float w = __expf(pm[i * 64 + t] - gm);
            s = fmaf(ps[i * 64 + t], w, s);
            #pragma unroll
            for (int c = 0; c < 16; c++)
                o[c] = fmaf(pacc[(i * 64 + t) * 16 + c], w, o[c]);
        }
        float inv = __fdividef(1.f, s);
        #pragma unroll
        for (int c = 0; c < 16; c++)
            g_attno[p][(size_t)(q0 + t) * 64 + h * 16 + c] = o[c] * inv;
    }
}

// ---------------------------------------------------------------------------
// K4c: inter out-proj, softplus, sample. grid 16, 256 threads.
// ---------------------------------------------------------------------------
__global__ __launch_bounds__(256) void k4c_proj(
    const float* __restrict__ wmo, const float* __restrict__ bmo,
    const float* __restrict__ wso, const float* __restrict__ bso,
    const float* __restrict__ eps_inter)
{
    __shared__ float Om[64][65];
    __shared__ float Os[64][65];
    int t = threadIdx.x;
    int r0 = blockIdx.x * 64;
    {
        int l = t >> 2, c = (t & 3) * 16;
        for (int i = 0; i < 16; i++) {
            Om[l][c + i] = g_attno[0][(size_t)(r0 + l) * 64 + c + i];
            Os[l][c + i] = g_attno[1][(size_t)(r0 + l) * 64 + c + i];
        }
    }
    __syncthreads();

    int lb = t >> 4, db = t & 15;
    float am[4][4], as[4][4];
    #pragma unroll
    for (int i = 0; i < 4; i++)
        #pragma unroll
        for (int j = 0; j < 4; j++) { am[i][j] = 0.f; as[i][j] = 0.f; }

    #pragma unroll 4
    for (int k = 0; k < 64; k++) {
        float om[4], os[4], wmv[4], wsv[4];
        #pragma unroll
        for (int i = 0; i < 4; i++) { om[i] = Om[lb * 4 + i][k]; os[i] = Os[lb * 4 + i][k]; }
        #pragma unroll
        for (int j = 0; j < 4; j++) {
            wmv[j] = __ldg(&wmo[(db * 4 + j) * 64 + k]);
            wsv[j] = __ldg(&wso[(db * 4 + j) * 64 + k]);
        }
        #pragma unroll
        for (int i = 0; i < 4; i++)
            #pragma unroll
            for (int j = 0; j < 4; j++) {
                am[i][j] = fmaf(om[i], wmv[j], am[i][j]);
                as[i][j] = fmaf(os[i], wsv[j], as[i][j]);
            }
    }
    #pragma unroll
    for (int i = 0; i < 4; i++) {
        int gi = r0 + lb * 4 + i;
        #pragma unroll
        for (int j = 0; j < 4; j++) {
            int d = db * 4 + j;
            float mu  = am[i][j] + bmo[d];
            float st  = softplusf(as[i][j] + bso[d] - 5.f);
            g_inter_mu[gi * 64 + d] = mu;
            g_inter_std[gi * 64 + d] = st;
            g_inter_sample[gi * 64 + d] = fmaf(st, eps_inter[gi * 64 + d], mu);
        }
    }
}

// ---------------------------------------------------------------------------
// K2: intra attention per group (QKV precomputed by k2a), out-proj,
// fused with ALL final scatter writes. 1 block / group, 256 threads.
// ---------------------------------------------------------------------------
__global__ __launch_bounds__(256) void k2_intra(
    const int* __restrict__ sets,
    const float* __restrict__ wmo, const float* __restrict__ bmo,
    const float* __restrict__ wso, const float* __restrict__ bso,
    const float* __restrict__ eps_intra,
    float* __restrict__ out_ac, float* __restrict__ out_mu, float* __restrict__ out_std)
{
    extern __shared__ float sm[];
    float* QKV  = sm;                  // [64][196]
    float* O    = QKV + 64 * 196;      // [64][65]
    float* Wo   = O + 64 * 65;         // [64][65]
    float* bout = Wo + 64 * 65;        // [64]
    float* MUb  = bout + 64;           // [64][64]
    int*   rows = (int*)(MUb + 64 * 64); // [64]

    int t = threadIdx.x;
    int g = blockIdx.x;
    if (t < 64) rows[t] = sets[g * 64 + t];
    __syncthreads();

    for (int p = 0; p < 2; p++) {
        const float* wOut = p ? wso : wmo;
        const float* bOut = p ? bso : bmo;
        __syncthreads();
        for (int v = t; v < 1024; v += 256) {
            int j = v >> 4; int cv = (v & 15) * 4;
            float4 w4 = *(const float4*)&wOut[j * 64 + cv];
            Wo[j * 65 + cv + 0] = w4.x; Wo[j * 65 + cv + 1] = w4.y;
            Wo[j * 65 + cv + 2] = w4.z; Wo[j * 65 + cv + 3] = w4.w;
        }
        if (t < 64) bout[t] = bOut[t];
        {
            int l = t >> 2, q4 = t & 3;
            const float* src = &g_qkv_all[(size_t)rows[l] * 384 + p * 192 + q4 * 48];
            float* dst = &QKV[l * 196 + q4 * 48];
            #pragma unroll
            for (int i = 0; i < 12; i++)
                *(float4*)&dst[i * 4] = *(const float4*)&src[i * 4];
        }
        __syncthreads();

        // attention: thread = (query i, head h), online softmax (branch form)
        {
            int i = t & 63, h = t >> 6;
            float q[16];
            #pragma unroll
            for (int c = 0; c < 16; c++) q[c] = QKV[i * 196 + h * 16 + c];
            float m = -1e30f, ssum = 0.f, acc[16];
            #pragma unroll
            for (int c = 0; c < 16; c++) acc[c] = 0.f;
            for (int j = 0; j < 64; j++) {
                float s = 0.f;
                const float* kr = &QKV[j * 196 + 64 + h * 16];
                #pragma unroll
                for (int c = 0; c < 16; c++) s = fmaf(q[c], kr[c], s);
                s *= 0.25f;
                const float* vr = &QKV[j * 196 + 128 + h * 16];
                if (s <= m) {
                    float w = __expf(s - m);
                    ssum += w;
                    #pragma unroll
                    for (int c = 0; c < 16; c++) acc[c] = fmaf(w, vr[c], acc[c]);
                } else {
                    float corr = __expf(m - s);
                    ssum = fmaf(ssum, corr, 1.f);
                    #pragma unroll
                    for (int c = 0; c < 16; c++) acc[c] = fmaf(acc[c], corr, vr[c]);
                    m = s;
                }
            }
            float inv = __fdividef(1.f, ssum);
            #pragma unroll
            for (int c = 0; c < 16; c++) O[i * 65 + h * 16 + c] = acc[c] * inv;
        }
        __syncthreads();

        // out proj (thread: 4 rows x 4 cols) + fused epilogue / global writes
        {
            int lb = t >> 4, db = t & 15;
            float acc[4][4];
            #pragma unroll
            for (int i = 0; i < 4; i++)
                #pragma unroll
                for (int j = 0; j < 4; j++) acc[i][j] = 0.f;
            #pragma unroll 4
            for (int k = 0; k < 64; k++) {
                float ov[4], wv[4];
                #pragma unroll
                for (int i = 0; i < 4; i++) ov[i] = O[(lb * 4 + i) * 65 + k];
                #pragma unroll
                for (int j = 0; j < 4; j++) wv[j] = Wo[(db * 4 + j) * 65 + k];
                #pragma unroll
                for (int i = 0; i < 4; i++)
                    #pragma unroll
                    for (int j = 0; j < 4; j++)
                        acc[i][j] = fmaf(ov[i], wv[j], acc[i][j]);
            }
            int d0 = db * 4;
            #pragma unroll
            for (int i = 0; i < 4; i++) {
                int l = lb * 4 + i;
                int row = rows[l];
                float4 v;
                v.x = acc[i][0] + bout[d0 + 0];
                v.y = acc[i][1] + bout[d0 + 1];
                v.z = acc[i][2] + bout[d0 + 2];
                v.w = acc[i][3] + bout[d0 + 3];
                if (p == 0) {
                    *(float4*)&MUb[l * 64 + d0] = v;
                    *(float4*)&out_mu[(size_t)row * 128 + d0] = v;
                    *(float4*)&out_mu[(size_t)row * 128 + 64 + d0] =
                        *(const float4*)&g_inter_mu[g * 64 + d0];
                    *(float4*)&out_ac[(size_t)row * 640 + 512 + d0] =
                        *(const float4*)&g_inter_sample[g * 64 + d0];
                } else {
                    float4 st;
                    st.x = softplusf(v.x - 5.f);
                    st.y = softplusf(v.y - 5.f);
                    st.z = softplusf(v.z - 5.f);
                    st.w = softplusf(v.w - 5.f);
                    float4 mu4 = *(const float4*)&MUb[l * 64 + d0];
                    float4 ep  = *(const float4*)&eps_intra[(size_t)row * 64 + d0];
                    float4 samp;
                    samp.x = fmaf(st.x, ep.x, mu4.x);
                    samp.y = fmaf(st.y, ep.y, mu4.y);
                    samp.z = fmaf(st.z, ep.z, mu4.z);
                    samp.w = fmaf(st.w, ep.w, mu4.w);
                    *(float4*)&out_std[(size_t)row * 128 + d0] = st;
                    *(float4*)&out_std[(size_t)row * 128 + 64 + d0] =
                        *(const float4*)&g_inter_std[g * 64 + d0];
                    *(float4*)&out_ac[(size_t)row * 640 + 576 + d0] = samp;
                }
            }
        }
    }
}

// ---------------------------------------------------------------------------
extern "C" void kernel_launch(void* const* d_in, const int* in_sizes, int n_in,
                              void* d_out, int out_size)
{
    (void)in_sizes; (void)n_in; (void)out_size;
    const float* obs        = (const float*)d_in[0];
    const int*   sets       = (const int*)  d_in[1];
    const float* eps_intra  = (const float*)d_in[2];
    const float* eps_inter  = (const float*)d_in[3];
    const float* local_w    = (const float*)d_in[4];
    const float* local_b    = (const float*)d_in[5];
    const float* inter_emb_w= (const float*)d_in[6];
    const float* inter_emb_b= (const float*)d_in[7];
    const float* intra_emb_w= (const float*)d_in[8];
    const float* intra_emb_b= (const float*)d_in[9];
    const float* amu_in_w   = (const float*)d_in[10];
    const float* amu_in_b   = (const float*)d_in[11];
    const float* amu_out_w  = (const float*)d_in[12];
    const float* amu_out_b  = (const float*)d_in[13];
    const float* astd_in_w  = (const float*)d_in[14];
    const float* astd_in_b  = (const float*)d_in[15];
    const float* astd_out_w = (const float*)d_in[16];
    const float* astd_out_b = (const float*)d_in[17];
    const float* emu_in_w   = (const float*)d_in[18];
    const float* emu_in_b   = (const float*)d_in[19];
    const float* emu_out_w  = (const float*)d_in[20];
    const float* emu_out_b  = (const float*)d_in[21];
    const float* estd_in_w  = (const float*)d_in[22];
    const float* estd_in_b  = (const float*)d_in[23];
    const float* estd_out_w = (const float*)d_in[24];
    const float* estd_out_b = (const float*)d_in[25];
    const float* attset_w   = (const float*)d_in[26];
    const float* attset_b   = (const float*)d_in[27];

    float* out_ac  = (float*)d_out;
    float* out_mu  = out_ac + (size_t)NN * 640;
    float* out_std = out_mu + (size_t)NN * 128;

    const int k2_smem  = (64*196 + 64*65 + 64*65 + 64 + 64*64) * 4 + 64 * 4;
    const int k4b_smem = (2 * 1024 * 16 + 8 * 64 * 2 + 8 * 64 * 16) * 4;
    cudaFuncSetAttribute(k2_intra, cudaFuncAttributeMaxDynamicSharedMemorySize, k2_smem);
    cudaFuncSetAttribute(k4b_attn, cudaFuncAttributeMaxDynamicSharedMemorySize, k4b_smem);
    cudaFuncSetAttribute(k1_mma, cudaFuncAttributeMaxDynamicSharedMemorySize, K1_SMEM);
    cudaFuncSetAttribute(k2a_qkv_gemm, cudaFuncAttributeMaxDynamicSharedMemorySize, K2A_SMEM);

    // split inputs into bf16 hi/lo
    k0_split_A<<<(NN * OBSD / 4 + 255) / 256, 256>>>((const float4*)obs);
    k0_split_W<<<640, 256>>>(local_w, local_b, inter_emb_w, inter_emb_b,
                             intra_emb_w, intra_emb_b);
    k0_split_Wq<<<384, 64>>>(amu_in_w, amu_in_b, astd_in_w, astd_in_b);

    dim3 g1(512, 10);
    k1_mma<<<g1, 256, K1_SMEM>>>(out_ac);
    dim3 g2a(512, 6);
    k2a_qkv_gemm<<<g2a, 256, K2A_SMEM>>>();

    k3_pool<<<GG, 256>>>(sets, attset_w, attset_b);
    dim3 g4a(16, 2);
    k4a_qkv<<<g4a, 256>>>(emu_in_w, emu_in_b, estd_in_w, estd_in_b);
    dim3 g4b(16, 4, 2);
    k4b_attn<<<g4b, 512, k4b_smem>>>();
    k4c_proj<<<16, 256>>>(emu_out_w, emu_out_b, estd_out_w, estd_out_b, eps_inter);
    k2_intra<<<GG, 256, k2_smem>>>(sets,
                                   amu_out_w, amu_out_b, astd_out_w, astd_out_b,
                                   eps_intra, out_ac, out_mu, out_std);
}

// round 13
// speedup vs baseline: 2.8367x; 1.0412x over previous
#include <cuda_runtime.h>
#include <cuda_bf16.h>
#include <math.h>
#include <stdint.h>

#define NN 65536
#define GG 1024
#define SSZ 64
#define DD 64
#define OBSD 256
#define HIDD 512

// ---------------- scratch (device globals; no allocations allowed) ----------
__device__ __align__(16) float g_inter_emb[NN * DD];
__device__ __align__(16) float g_pooled[GG * DD];
__device__ __align__(16) float g_qkv[2][GG * 3 * DD];
__device__ __align__(16) float g_attno[2][GG * DD];
__device__ __align__(16) float g_inter_mu[GG * DD];
__device__ __align__(16) float g_inter_std[GG * DD];
__device__ __align__(16) float g_inter_sample[GG * DD];

// bf16 hi/lo split operands
__device__ __align__(16) __nv_bfloat16 g_Ah[(size_t)NN * OBSD];
__device__ __align__(16) __nv_bfloat16 g_Al[(size_t)NN * OBSD];
__device__ __align__(16) __nv_bfloat16 g_Wh[640 * OBSD];
__device__ __align__(16) __nv_bfloat16 g_Wl[640 * OBSD];
__device__ float g_bias[640];

// intra_emb as bf16 hi/lo (input to k2a GEMM)
__device__ __align__(16) __nv_bfloat16 g_Eh[(size_t)NN * DD];
__device__ __align__(16) __nv_bfloat16 g_El[(size_t)NN * DD];
// packed intra in-proj weights [384=192mu+192std][64] hi/lo + bias
__device__ __align__(16) __nv_bfloat16 g_Wqh[384 * DD];
__device__ __align__(16) __nv_bfloat16 g_Wql[384 * DD];
__device__ float g_qbias[384];
// QKV (bias included) for all agents: [65536][384] (0..191 mu, 192..383 std)
__device__ __align__(16) float g_qkv_all[(size_t)NN * 384];

__device__ __forceinline__ float softplusf(float x) {
    return (x > 20.f) ? x : __logf(1.f + __expf(x));
}
__device__ __forceinline__ float ftanh(float x) {
    float ax = fabsf(x);
    float t = __expf(-2.f * ax);
    float r = __fdividef(1.f - t, 1.f + t);
    return copysignf(r, x);
}

__device__ __forceinline__ uint32_t smem_u32(const void* p) {
    uint32_t a;
    asm("{ .reg .u64 t; cvta.to.shared.u64 t, %1; cvt.u32.u64 %0, t; }" : "=r"(a) : "l"(p));
    return a;
}
__device__ __forceinline__ uint32_t swz128(uint32_t off) {
    return off ^ ((off >> 3) & 0x70);
}
__device__ __forceinline__ uint32_t swz64(uint32_t off) {
    return off ^ ((off >> 3) & 0x30);
}
__device__ __forceinline__ void ldm_x4(uint32_t* r, uint32_t addr) {
    asm volatile("ldmatrix.sync.aligned.m8n8.x4.shared.b16 {%0,%1,%2,%3}, [%4];"
        : "=r"(r[0]), "=r"(r[1]), "=r"(r[2]), "=r"(r[3]) : "r"(addr));
}
__device__ __forceinline__ void mma16816(float* d, const uint32_t* a, const uint32_t* b) {
    asm volatile(
        "mma.sync.aligned.m16n8k16.row.col.f32.bf16.bf16.f32 "
        "{%0,%1,%2,%3}, {%4,%5,%6,%7}, {%8,%9}, {%0,%1,%2,%3};"
        : "+f"(d[0]), "+f"(d[1]), "+f"(d[2]), "+f"(d[3])
        : "r"(a[0]), "r"(a[1]), "r"(a[2]), "r"(a[3]), "r"(b[0]), "r"(b[1]));
}
__device__ __forceinline__ void cpasync16(uint32_t dst, const void* src) {
    asm volatile("cp.async.cg.shared.global [%0], [%1], 16;" :: "r"(dst), "l"(src));
}
#define CP_COMMIT() asm volatile("cp.async.commit_group;" ::: "memory")
#define CP_WAIT2()  asm volatile("cp.async.wait_group 2;" ::: "memory")
#define CP_WAIT1()  asm volatile("cp.async.wait_group 1;" ::: "memory")
#define CP_WAIT0()  asm volatile("cp.async.wait_group 0;" ::: "memory")

// ---------------------------------------------------------------------------
// K0a: split obs fp32 -> bf16 hi/lo
// ---------------------------------------------------------------------------
__global__ __launch_bounds__(256) void k0_split_A(const float4* __restrict__ obs4) {
    size_t i = (size_t)blockIdx.x * 256 + threadIdx.x;
    float4 v = obs4[i];
    size_t b = i * 4;
    __nv_bfloat16 h0 = __float2bfloat16(v.x);
    __nv_bfloat16 h1 = __float2bfloat16(v.y);
    __nv_bfloat16 h2 = __float2bfloat16(v.z);
    __nv_bfloat16 h3 = __float2bfloat16(v.w);
    __nv_bfloat16 l0 = __float2bfloat16(v.x - __bfloat162float(h0));
    __nv_bfloat16 l1 = __float2bfloat16(v.y - __bfloat162float(h1));
    __nv_bfloat16 l2 = __float2bfloat16(v.z - __bfloat162float(h2));
    __nv_bfloat16 l3 = __float2bfloat16(v.w - __bfloat162float(h3));
    *(__nv_bfloat162*)&g_Ah[b]     = __halves2bfloat162(h0, h1);
    *(__nv_bfloat162*)&g_Ah[b + 2] = __halves2bfloat162(h2, h3);
    *(__nv_bfloat162*)&g_Al[b]     = __halves2bfloat162(l0, l1);
    *(__nv_bfloat162*)&g_Al[b + 2] = __halves2bfloat162(l2, l3);
}

// K0b: pack embed weights [640][256] = [local(512); inter(64); intra(64)] + bias
__global__ __launch_bounds__(256) void k0_split_W(
    const float* __restrict__ lw, const float* __restrict__ lb,
    const float* __restrict__ iw, const float* __restrict__ ib,
    const float* __restrict__ tw, const float* __restrict__ tb)
{
    int row = blockIdx.x, col = threadIdx.x;
    const float* src; const float* bs; int r;
    if (row < 512)      { src = lw; bs = lb; r = row; }
    else if (row < 576) { src = iw; bs = ib; r = row - 512; }
    else                { src = tw; bs = tb; r = row - 576; }
    float x = src[r * OBSD + col];
    __nv_bfloat16 h = __float2bfloat16(x);
    g_Wh[row * OBSD + col] = h;
    g_Wl[row * OBSD + col] = __float2bfloat16(x - __bfloat162float(h));
    if (col == 0) g_bias[row] = bs[r];
}

// K0c: pack intra in-proj weights [384][64] (mu 0..191, std 192..383) + bias
__global__ __launch_bounds__(64) void k0_split_Wq(
    const float* __restrict__ wmi, const float* __restrict__ bmi,
    const float* __restrict__ wsi, const float* __restrict__ bsi)
{
    int row = blockIdx.x, col = threadIdx.x;
    const float* src; const float* bs; int r;
    if (row < 192) { src = wmi; bs = bmi; r = row; }
    else           { src = wsi; bs = bsi; r = row - 192; }
    float x = src[r * 64 + col];
    __nv_bfloat16 h = __float2bfloat16(x);
    g_Wqh[row * 64 + col] = h;
    g_Wql[row * 64 + col] = __float2bfloat16(x - __bfloat162float(h));
    if (col == 0) g_qbias[row] = bs[r];
}

// ---------------------------------------------------------------------------
// K1: mma.sync bf16-split GEMM  C[65536,640] = tanh(A @ W^T + b).
// grid (512, 10), block 256 (8 warps = 4M x 2N), launch_bounds(256,2).
// Tile M=128, N=64. 8 K-chunks of 32, 3-stage cp.async pipeline, SW64 swizzle.
// nb 0..7 -> out_ac, nb==8 -> g_inter_emb fp32, nb==9 -> g_Eh/g_El bf16 split.
// ---------------------------------------------------------------------------
#define K1_AH 0
#define K1_AL 8192
#define K1_BH 16384
#define K1_BL 20480
#define K1_BUF 24576
#define K1_SMEM (3 * K1_BUF)

__global__ __launch_bounds__(256, 2) void k1_mma(float* __restrict__ out_ac)
{
    extern __shared__ char sm1[];
    uint32_t smb = smem_u32(sm1);
    int t = threadIdx.x;
    int lane = t & 31, wid = t >> 5;
    int mwarp = wid & 3, nwarp = wid >> 2;
    int row0 = blockIdx.x * 128;
    int nb = blockIdx.y;
    int cb = nb * 64;

    int arow = t >> 1, aseg = (t & 1) * 2;   // A: 128 rows, 2 thr/row x 2 chunks(16B)
    int brow = t >> 2, bseg = t & 3;         // B: 64 rows, 4 thr/row x 1 chunk

    uint32_t a_row_im = (uint32_t)(mwarp * 32 + (lane & 15));
    uint32_t a_kb_im  = (uint32_t)((lane >> 4) * 16);
    uint32_t b_row_im = (uint32_t)(nwarp * 32 + ((lane >> 4) & 1) * 8 + (lane & 7));
    uint32_t b_kb_im  = (uint32_t)(((lane >> 3) & 1) * 16);

    auto stage = [&](int buf, int ck) {
        int k0 = ck * 32;
        uint32_t base = smb + buf * K1_BUF;
        size_t aoff = (size_t)(row0 + arow) * OBSD + k0 + aseg * 8;
        #pragma unroll
        for (int i = 0; i < 2; i++) {
            uint32_t so = swz64((uint32_t)arow * 64 + (aseg + i) * 16);
            cpasync16(base + K1_AH + so, &g_Ah[aoff + i * 8]);
            cpasync16(base + K1_AL + so, &g_Al[aoff + i * 8]);
        }
        size_t boff = (size_t)(cb + brow) * OBSD + k0 + bseg * 8;
        uint32_t so = swz64((uint32_t)brow * 64 + bseg * 16);
        cpasync16(base + K1_BH + so, &g_Wh[boff]);
        cpasync16(base + K1_BL + so, &g_Wl[boff]);
    };

    float acc[2][4][4];
    #pragma unroll
    for (int mt = 0; mt < 2; mt++)
        #pragma unroll
        for (int nt = 0; nt < 4; nt++)
            #pragma unroll
            for (int e = 0; e < 4; e++) acc[mt][nt][e] = 0.f;

    stage(0, 0);
    CP_COMMIT();
    stage(1, 1);
    CP_COMMIT();

    for (int ck = 0; ck < 8; ck++) {
        int buf = ck % 3;
        __syncthreads();           // all warps done computing chunk ck-1
        if (ck + 2 < 8) {
            stage((ck + 2) % 3, ck + 2);
            CP_COMMIT();
            CP_WAIT2();            // chunk ck complete
        } else if (ck + 1 < 8) {
            CP_WAIT1();
        } else {
            CP_WAIT0();
        }
        __syncthreads();           // staged data visible to all warps

        uint32_t base = smb + buf * K1_BUF;
        #pragma unroll
        for (int ks = 0; ks < 2; ks++) {
            uint32_t aH[2][4], aL[2][4];
            #pragma unroll
            for (int mt = 0; mt < 2; mt++) {
                uint32_t off = swz64((a_row_im + mt * 16) * 64 + ks * 32 + a_kb_im);
                ldm_x4(aH[mt], base + K1_AH + off);
                ldm_x4(aL[mt], base + K1_AL + off);
            }
            uint32_t bH[2][4], bL[2][4];
            #pragma unroll
            for (int np = 0; np < 2; np++) {
                uint32_t off = swz64((b_row_im + np * 16) * 64 + ks * 32 + b_kb_im);
                ldm_x4(bH[np], base + K1_BH + off);
                ldm_x4(bL[np], base + K1_BL + off);
            }
            #pragma unroll
            for (int mt = 0; mt < 2; mt++)
                #pragma unroll
                for (int np = 0; np < 2; np++) {
                    mma16816(acc[mt][np * 2 + 0], aH[mt], bH[np] + 0);
                    mma16816(acc[mt][np * 2 + 1], aH[mt], bH[np] + 2);
                    mma16816(acc[mt][np * 2 + 0], aH[mt], bL[np] + 0);
                    mma16816(acc[mt][np * 2 + 1], aH[mt], bL[np] + 2);
                    mma16816(acc[mt][np * 2 + 0], aL[mt], bH[np] + 0);
                    mma16816(acc[mt][np * 2 + 1], aL[mt], bH[np] + 2);
                }
        }
    }

    // epilogue: bias + tanh
    #pragma unroll
    for (int mt = 0; mt < 2; mt++) {
        int rbase = row0 + mwarp * 32 + mt * 16 + (lane >> 2);
        #pragma unroll
        for (int nt = 0; nt < 4; nt++) {
            int colT = nwarp * 32 + nt * 8 + (lane & 3) * 2;
            float2 b2 = *(const float2*)&g_bias[cb + colT];
            #pragma unroll
            for (int rh = 0; rh < 2; rh++) {
                int row = rbase + rh * 8;
                float2 o;
                o.x = ftanh(acc[mt][nt][rh * 2 + 0] + b2.x);
                o.y = ftanh(acc[mt][nt][rh * 2 + 1] + b2.y);
                if (nb < 8) {
                    *(float2*)&out_ac[(size_t)row * 640 + cb + colT] = o;
                } else if (nb == 8) {
                    *(float2*)&g_inter_emb[(size_t)row * 64 + colT] = o;
                } else {
                    __nv_bfloat16 h0 = __float2bfloat16(o.x);
                    __nv_bfloat16 h1 = __float2bfloat16(o.y);
                    __nv_bfloat16 l0 = __float2bfloat16(o.x - __bfloat162float(h0));
                    __nv_bfloat16 l1 = __float2bfloat16(o.y - __bfloat162float(h1));
                    *(__nv_bfloat162*)&g_Eh[(size_t)row * 64 + colT] = __halves2bfloat162(h0, h1);
                    *(__nv_bfloat162*)&g_El[(size_t)row * 64 + colT] = __halves2bfloat162(l0, l1);
                }
            }
        }
    }
}

// ---------------------------------------------------------------------------
// K2a: mma.sync bf16-split GEMM  QKV_all[65536,384] = E @ Wq^T + qbias.
// grid (512, 6), block 256 (8 warps = 4M x 2N), launch_bounds(256,2).
// Tile M=128, N=64, K=64 (single chunk), SW128.
// ---------------------------------------------------------------------------
#define K2A_AH 0
#define K2A_AL 16384
#define K2A_BH 32768
#define K2A_BL 40960
#define K2A_SMEM 49152

__global__ __launch_bounds__(256, 2) void k2a_qkv_gemm()
{
    extern __shared__ char sm2[];
    uint32_t smb = smem_u32(sm2);
    int t = threadIdx.x;
    int lane = t & 31, wid = t >> 5;
    int mwarp = wid & 3, nwarp = wid >> 2;
    int row0 = blockIdx.x * 128;
    int cb = blockIdx.y * 64;

    uint32_t a_row_im = (uint32_t)(mwarp * 32 + (lane & 15));
    uint32_t a_kb_im  = (uint32_t)((lane >> 4) * 16);
    uint32_t b_row_im = (uint32_t)(nwarp * 32 + ((lane >> 4) & 1) * 8 + (lane & 7));
    uint32_t b_kb_im  = (uint32_t)(((lane >> 3) & 1) * 16);

    {
        int arow = t >> 1, akseg = t & 1;
        size_t aoff = (size_t)(row0 + arow) * 64 + akseg * 32;
        #pragma unroll
        for (int i = 0; i < 4; i++) {
            uint32_t so = swz128((uint32_t)arow * 128 + akseg * 64 + i * 16);
            cpasync16(smb + K2A_AH + so, &g_Eh[aoff + i * 8]);
            cpasync16(smb + K2A_AL + so, &g_El[aoff + i * 8]);
        }
        int brow = t >> 2, bkseg = t & 3;
        size_t boff = (size_t)(cb + brow) * 64 + bkseg * 16;
        #pragma unroll
        for (int i = 0; i < 2; i++) {
            uint32_t so = swz128((uint32_t)brow * 128 + bkseg * 32 + i * 16);
            cpasync16(smb + K2A_BH + so, &g_Wqh[boff + i * 8]);
            cpasync16(smb + K2A_BL + so, &g_Wql[boff + i * 8]);
        }
    }
    CP_COMMIT();
    CP_WAIT0();
    __syncthreads();

    float acc[2][4][4];
    #pragma unroll
    for (int mt = 0; mt < 2; mt++)
        #pragma unroll
        for (int nt = 0; nt < 4; nt++)
            #pragma unroll
            for (int e = 0; e < 4; e++) acc[mt][nt][e] = 0.f;

    #pragma unroll
    for (int ks = 0; ks < 4; ks++) {
        uint32_t aH[2][4], aL[2][4];
        #pragma unroll
        for (int mt = 0; mt < 2; mt++) {
            uint32_t off = swz128((a_row_im + mt * 16) * 128 + ks * 32 + a_kb_im);
            ldm_x4(aH[mt], smb + K2A_AH + off);
            ldm_x4(aL[mt], smb + K2A_AL + off);
        }
        uint32_t bH[2][4], bL[2][4];
        #pragma unroll
        for (int np = 0; np < 2; np++) {
            uint32_t off = swz128((b_row_im + np * 16) * 128 + ks * 32 + b_kb_im);
            ldm_x4(bH[np], smb + K2A_BH + off);
            ldm_x4(bL[np], smb + K2A_BL + off);
        }
        #pragma unroll
        for (int mt = 0; mt < 2; mt++)
            #pragma unroll
            for (int np = 0; np < 2; np++) {
                mma16816(acc[mt][np * 2 + 0], aH[mt], bH[np] + 0);
                mma16816(acc[mt][np * 2 + 1], aH[mt], bH[np] + 2);
                mma16816(acc[mt][np * 2 + 0], aH[mt], bL[np] + 0);
                mma16816(acc[mt][np * 2 + 1], aH[mt], bL[np] + 2);
                mma16816(acc[mt][np * 2 + 0], aL[mt], bH[np] + 0);
                mma16816(acc[mt][np * 2 + 1], aL[mt], bH[np] + 2);
            }
    }

    #pragma unroll
    for (int mt = 0; mt < 2; mt++) {
        int rbase = row0 + mwarp * 32 + mt * 16 + (lane >> 2);
        #pragma unroll
        for (int nt = 0; nt < 4; nt++) {
            int colg = cb + nwarp * 32 + nt * 8 + (lane & 3) * 2;
            float2 b2 = *(const float2*)&g_qbias[colg];
            #pragma unroll
            for (int rh = 0; rh < 2; rh++) {
                int row = rbase + rh * 8;
                float2 o;
                o.x = acc[mt][nt][rh * 2 + 0] + b2.x;
                o.y = acc[mt][nt][rh * 2 + 1] + b2.y;
                *(float2*)&g_qkv_all[(size_t)row * 384 + colg] = o;
            }
        }
    }
}

// ---------------------------------------------------------------------------
// K3: softmax pooling per group. 1 block / group, 256 threads.
// ---------------------------------------------------------------------------
__global__ __launch_bounds__(256) void k3_pool(
    const int* __restrict__ sets,
    const float* __restrict__ aw, const float* __restrict__ ab)
{
    __shared__ float X[64][65];
    __shared__ float wgt[64];
    __shared__ int rows[64];
    __shared__ float wm[2], wsum[2];
    __shared__ float red[4][64];

    int t = threadIdx.x;
    int g = blockIdx.x;
    if (t < 64) rows[t] = sets[g * 64 + t];
    __syncthreads();
    {
        int l = t >> 2, c = (t & 3) * 16;
        const float* src = &g_inter_emb[(size_t)rows[l] * 64 + c];
        #pragma unroll
        for (int i = 0; i < 4; i++) {
            float4 v = *(const float4*)&src[i * 4];
            X[l][c + i * 4 + 0] = v.x;
            X[l][c + i * 4 + 1] = v.y;
            X[l][c + i * 4 + 2] = v.z;
            X[l][c + i * 4 + 3] = v.w;
        }
    }
    __syncthreads();

    float lg = 0.f, e = 0.f;
    if (t < 64) {
        lg = ab[0];
        #pragma unroll 8
        for (int k = 0; k < 64; k++) lg = fmaf(X[t][k], aw[k], lg);
        float m = lg;
        #pragma unroll
        for (int o = 16; o; o >>= 1) m = fmaxf(m, __shfl_xor_sync(0xffffffffu, m, o));
        if ((t & 31) == 0) wm[t >> 5] = m;
    }
    __syncthreads();
    if (t < 64) {
        float m = fmaxf(wm[0], wm[1]);
        e = __expf(lg - m);
        float s = e;
        #pragma unroll
        for (int o = 16; o; o >>= 1) s += __shfl_xor_sync(0xffffffffu, s, o);
        if ((t & 31) == 0) wsum[t >> 5] = s;
    }
    __syncthreads();
    if (t < 64) wgt[t] = e / (wsum[0] + wsum[1]);
    __syncthreads();

    {
        int d = t & 63, seg = t >> 6;
        float acc = 0.f;
        #pragma unroll
        for (int k = seg * 16; k < seg * 16 + 16; k++)
            acc = fmaf(wgt[k], X[k][d], acc);
        red[seg][d] = acc;
    }
    __syncthreads();
    if (t < 64)
        g_pooled[g * 64 + t] = red[0][t] + red[1][t] + red[2][t] + red[3][t];
}

// ---------------------------------------------------------------------------
// K4a: inter QKV = pooled @ w_in^T + b.  grid (16, 2[mu/std]), 256 thr.
// ---------------------------------------------------------------------------
__global__ __launch_bounds__(256) void k4a_qkv(
    const float* __restrict__ wmi, const float* __restrict__ bmi,
    const float* __restrict__ wsi, const float* __restrict__ bsi)
{
    __shared__ float X[64][65];
    int t = threadIdx.x;
    int r0 = blockIdx.x * 64;
    int p = blockIdx.y;
    const float* Wi = p ? wsi : wmi;
    const float* bi = p ? bsi : bmi;

    {
        int l = t >> 2, c = (t & 3) * 16;
        #pragma unroll
        for (int i = 0; i < 4; i++) {
            float4 v = *(const float4*)&g_pooled[(r0 + l) * 64 + c + i * 4];
            X[l][c + i * 4 + 0] = v.x;
            X[l][c + i * 4 + 1] = v.y;
            X[l][c + i * 4 + 2] = v.z;
            X[l][c + i * 4 + 3] = v.w;
        }
    }
    __syncthreads();

    int l  = t & 63;
    int jb = t >> 6;
    for (int jj = 0; jj < 48; jj++) {
        int j = jb * 48 + jj;
        float acc = bi[j];
        #pragma unroll 8
        for (int k = 0; k < 64; k++) acc = fmaf(X[l][k], __ldg(&Wi[j * 64 + k]), acc);
        g_qkv[p][(r0 + l) * 192 + j] = acc;
    }
}

// ---------------------------------------------------------------------------
// K4b: inter attention (L=1024, dh=16). grid (16 qtiles, 4 heads, 2 passes),
// 512 threads: 8 key-chunks of 128 keys, partial online softmax + combine.
// float4 K/V smem loads.
// ---------------------------------------------------------------------------
__global__ __launch_bounds__(512) void k4b_attn()
{
    extern __shared__ float sm4b[];
    float* Ks   = sm4b;
    float* Vs   = Ks + 1024 * 16;
    float* pm   = Vs + 1024 * 16;
    float* ps   = pm + 8 * 64;
    float* pacc = ps + 8 * 64;

    int t  = threadIdx.x;
    int kc = t >> 6, qi = t & 63;
    int q0 = blockIdx.x * 64;
    int h  = blockIdx.y;
    int p  = blockIdx.z;
    const float* QKV = g_qkv[p];

    for (int r = t; r < 1024; r += 512) {
        #pragma unroll
        for (int i = 0; i < 4; i++) {
            *(float4*)&Ks[r * 16 + i * 4] =
                *(const float4*)&QKV[(size_t)r * 192 + 64 + h * 16 + i * 4];
            *(float4*)&Vs[r * 16 + i * 4] =
                *(const float4*)&QKV[(size_t)r * 192 + 128 + h * 16 + i * 4];
        }
    }
    __syncthreads();

    float4 q[4];
    #pragma unroll
    for (int i = 0; i < 4; i++)
        q[i] = *(const float4*)&QKV[(size_t)(q0 + qi) * 192 + h * 16 + i * 4];

    float m = -1e30f, ssum = 0.f, acc[16];
    #pragma unroll
    for (int i = 0; i < 16; i++) acc[i] = 0.f;

    int jbase = kc * 128;
    for (int j = jbase; j < jbase + 128; j++) {
        const float4* kr = (const float4*)&Ks[j * 16];
        float4 k0 = kr[0], k1 = kr[1], k2 = kr[2], k3 = kr[3];
        float s = q[0].x * k0.x;
        s = fmaf(q[0].y, k0.y, s); s = fmaf(q[0].z, k0.z, s); s = fmaf(q[0].w, k0.w, s);
        s = fmaf(q[1].x, k1.x, s); s = fmaf(q[1].y, k1.y, s);
        s = fmaf(q[1].z, k1.z, s); s = fmaf(q[1].w, k1.w, s);
        s = fmaf(q[2].x, k2.x, s); s = fmaf(q[2].y, k2.y, s);
        s = fmaf(q[2].z, k2.z, s); s = fmaf(q[2].w, k2.w, s);
        s = fmaf(q[3].x, k3.x, s); s = fmaf(q[3].y, k3.y, s);
        s = fmaf(q[3].z, k3.z, s); s = fmaf(q[3].w, k3.w, s);
        s *= 0.25f;
        const float4* vr = (const float4*)&Vs[j * 16];
        float4 v0 = vr[0], v1 = vr[1], v2 = vr[2], v3 = vr[3];
        float vv[16] = {v0.x, v0.y, v0.z, v0.w, v1.x, v1.y, v1.z, v1.w,
                        v2.x, v2.y, v2.z, v2.w, v3.x, v3.y, v3.z, v3.w};
        if (s <= m) {
            float w = __expf(s - m);
            ssum += w;
            #pragma unroll
            for (int c = 0; c < 16; c++) acc[c] = fmaf(w, vv[c], acc[c]);
        } else {
            float corr = __expf(m - s);
            ssum = fmaf(ssum, corr, 1.f);
            #pragma unroll
            for (int c = 0; c < 16; c++) acc[c] = fmaf(acc[c], corr, vv[c]);
            m = s;
        }
    }
    pm[kc * 64 + qi] = m;
    ps[kc * 64 + qi] = ssum;
    #pragma unroll
    for (int c = 0; c < 16; c++) pacc[(kc * 64 + qi) * 16 + c] = acc[c];
    __syncthreads();

    if (t < 64) {
        float gm = -1e30f;
        #pragma unroll
        for (int i = 0; i < 8; i++) gm = fmaxf(gm, pm[i * 64 + t]);
        float s = 0.f, o[16];
        #pragma unroll
        for (int c = 0; c < 16; c++) o[c] = 0.f;
        #pragma unroll
        for (int i = 0; i < 8; i++) {
            float w = __expf(pm[i * 64 + t] - gm);
            s = fmaf(ps[i * 64 + t], w, s);
            #pragma unroll
            for (int c = 0; c < 16; c++)
                o[c] = fmaf(pacc[(i * 64 + t) * 16 + c], w, o[c]);
        }
        float inv = __fdividef(1.f, s);
        #pragma unroll
        for (int c = 0; c < 16; c++)
            g_attno[p][(size_t)(q0 + t) * 64 + h * 16 + c] = o[c] * inv;
    }
}

// ---------------------------------------------------------------------------
// K4c: inter out-proj, softplus, sample. grid 16, 256 threads.
// ---------------------------------------------------------------------------
__global__ __launch_bounds__(256) void k4c_proj(
    const float* __restrict__ wmo, const float* __restrict__ bmo,
    const float* __restrict__ wso, const float* __restrict__ bso,
    const float* __restrict__ eps_inter)
{
    __shared__ float Om[64][65];
    __shared__ float Os[64][65];
    int t = threadIdx.x;
    int r0 = blockIdx.x * 64;
    {
        int l = t >> 2, c = (t & 3) * 16;
        for (int i = 0; i < 16; i++) {
            Om[l][c + i] = g_attno[0][(size_t)(r0 + l) * 64 + c + i];
            Os[l][c + i] = g_attno[1][(size_t)(r0 + l) * 64 + c + i];
        }
    }
    __syncthreads();

    int lb = t >> 4, db = t & 15;
    float am[4][4], as[4][4];
    #pragma unroll
    for (int i = 0; i < 4; i++)
        #pragma unroll
        for (int j = 0; j < 4; j++) { am[i][j] = 0.f; as[i][j] = 0.f; }

    #pragma unroll 4
    for (int k = 0; k < 64; k++) {
        float om[4], os[4], wmv[4], wsv[4];
        #pragma unroll
        for (int i = 0; i < 4; i++) { om[i] = Om[lb * 4 + i][k]; os[i] = Os[lb * 4 + i][k]; }
        #pragma unroll
        for (int j = 0; j < 4; j++) {
            wmv[j] = __ldg(&wmo[(db * 4 + j) * 64 + k]);
            wsv[j] = __ldg(&wso[(db * 4 + j) * 64 + k]);
        }
        #pragma unroll
        for (int i = 0; i < 4; i++)
            #pragma unroll
            for (int j = 0; j < 4; j++) {
                am[i][j] = fmaf(om[i], wmv[j], am[i][j]);
                as[i][j] = fmaf(os[i], wsv[j], as[i][j]);
            }
    }
    #pragma unroll
    for (int i = 0; i < 4; i++) {
        int gi = r0 + lb * 4 + i;
        #pragma unroll
        for (int j = 0; j < 4; j++) {
            int d = db * 4 + j;
            float mu  = am[i][j] + bmo[d];
            float st  = softplusf(as[i][j] + bso[d] - 5.f);
            g_inter_mu[gi * 64 + d] = mu;
            g_inter_std[gi * 64 + d] = st;
            g_inter_sample[gi * 64 + d] = fmaf(st, eps_inter[gi * 64 + d], mu);
        }
    }
}

// ---------------------------------------------------------------------------
// K2: intra attention per group (QKV precomputed by k2a), out-proj,
// fused with ALL final scatter writes. 1 block / group, 256 threads.
// float4 K/V smem loads in attention loop.
// ---------------------------------------------------------------------------
__global__ __launch_bounds__(256) void k2_intra(
    const int* __restrict__ sets,
    const float* __restrict__ wmo, const float* __restrict__ bmo,
    const float* __restrict__ wso, const float* __restrict__ bso,
    const float* __restrict__ eps_intra,
    float* __restrict__ out_ac, float* __restrict__ out_mu, float* __restrict__ out_std)
{
    extern __shared__ float sm[];
    float* QKV  = sm;                  // [64][196]
    float* O    = QKV + 64 * 196;      // [64][65]
    float* Wo   = O + 64 * 65;         // [64][65]
    float* bout = Wo + 64 * 65;        // [64]
    float* MUb  = bout + 64;           // [64][64]
    int*   rows = (int*)(MUb + 64 * 64); // [64]

    int t = threadIdx.x;
    int g = blockIdx.x;
    if (t < 64) rows[t] = sets[g * 64 + t];
    __syncthreads();

    for (int p = 0; p < 2; p++) {
        const float* wOut = p ? wso : wmo;
        const float* bOut = p ? bso : bmo;
        __syncthreads();
        for (int v = t; v < 1024; v += 256) {
            int j = v >> 4; int cv = (v & 15) * 4;
            float4 w4 = *(const float4*)&wOut[j * 64 + cv];
            Wo[j * 65 + cv + 0] = w4.x; Wo[j * 65 + cv + 1] = w4.y;
            Wo[j * 65 + cv + 2] = w4.z; Wo[j * 65 + cv + 3] = w4.w;
        }
        if (t < 64) bout[t] = bOut[t];
        {
            int l = t >> 2, q4 = t & 3;
            const float* src = &g_qkv_all[(size_t)rows[l] * 384 + p * 192 + q4 * 48];
            float* dst = &QKV[l * 196 + q4 * 48];
            #pragma unroll
            for (int i = 0; i < 12; i++)
                *(float4*)&dst[i * 4] = *(const float4*)&src[i * 4];
        }
        __syncthreads();

        // attention: thread = (query i, head h), online softmax (branch form)
        {
            int i = t & 63, h = t >> 6;
            float4 q[4];
            #pragma unroll
            for (int c = 0; c < 4; c++)
                q[c] = *(const float4*)&QKV[i * 196 + h * 16 + c * 4];
            float m = -1e30f, ssum = 0.f, acc[16];
            #pragma unroll
            for (int c = 0; c < 16; c++) acc[c] = 0.f;
            for (int j = 0; j < 64; j++) {
                const float4* kr = (const float4*)&QKV[j * 196 + 64 + h * 16];
                float4 k0 = kr[0], k1 = kr[1], k2 = kr[2], k3 = kr[3];
                float s = q[0].x * k0.x;
                s = fmaf(q[0].y, k0.y, s); s = fmaf(q[0].z, k0.z, s); s = fmaf(q[0].w, k0.w, s);
                s = fmaf(q[1].x, k1.x, s); s = fmaf(q[1].y, k1.y, s);
                s = fmaf(q[1].z, k1.z, s); s = fmaf(q[1].w, k1.w, s);
                s = fmaf(q[2].x, k2.x, s); s = fmaf(q[2].y, k2.y, s);
                s = fmaf(q[2].z, k2.z, s); s = fmaf(q[2].w, k2.w, s);
                s = fmaf(q[3].x, k3.x, s); s = fmaf(q[3].y, k3.y, s);
                s = fmaf(q[3].z, k3.z, s); s = fmaf(q[3].w, k3.w, s);
                s *= 0.25f;
                const float4* vr = (const float4*)&QKV[j * 196 + 128 + h * 16];
                float4 v0 = vr[0], v1 = vr[1], v2 = vr[2], v3 = vr[3];
                float vv[16] = {v0.x, v0.y, v0.z, v0.w, v1.x, v1.y, v1.z, v1.w,
                                v2.x, v2.y, v2.z, v2.w, v3.x, v3.y, v3.z, v3.w};
                if (s <= m) {
                    float w = __expf(s - m);
                    ssum += w;
                    #pragma unroll
                    for (int c = 0; c < 16; c++) acc[c] = fmaf(w, vv[c], acc[c]);
                } else {
                    float corr = __expf(m - s);
                    ssum = fmaf(ssum, corr, 1.f);
                    #pragma unroll
                    for (int c = 0; c < 16; c++) acc[c] = fmaf(acc[c], corr, vv[c]);
                    m = s;
                }
            }
            float inv = __fdividef(1.f, ssum);
            #pragma unroll
            for (int c = 0; c < 16; c++) O[i * 65 + h * 16 + c] = acc[c] * inv;
        }
        __syncthreads();

        // out proj (thread: 4 rows x 4 cols) + fused epilogue / global writes
        {
            int lb = t >> 4, db = t & 15;
            float acc[4][4];
            #pragma unroll
            for (int i = 0; i < 4; i++)
                #pragma unroll
                for (int j = 0; j < 4; j++) acc[i][j] = 0.f;
            #pragma unroll 4
            for (int k = 0; k < 64; k++) {
                float ov[4], wv[4];
                #pragma unroll
                for (int i = 0; i < 4; i++) ov[i] = O[(lb * 4 + i) * 65 + k];
                #pragma unroll
                for (int j = 0; j < 4; j++) wv[j] = Wo[(db * 4 + j) * 65 + k];
                #pragma unroll
                for (int i = 0; i < 4; i++)
                    #pragma unroll
                    for (int j = 0; j < 4; j++)
                        acc[i][j] = fmaf(ov[i], wv[j], acc[i][j]);
            }
            int d0 = db * 4;
            #pragma unroll
            for (int i = 0; i < 4; i++) {
                int l = lb * 4 + i;
                int row = rows[l];
                float4 v;
                v.x = acc[i][0] + bout[d0 + 0];
                v.y = acc[i][1] + bout[d0 + 1];
                v.z = acc[i][2] + bout[d0 + 2];
                v.w = acc[i][3] + bout[d0 + 3];
                if (p == 0) {
                    *(float4*)&MUb[l * 64 + d0] = v;
                    *(float4*)&out_mu[(size_t)row * 128 + d0] = v;
                    *(float4*)&out_mu[(size_t)row * 128 + 64 + d0] =
                        *(const float4*)&g_inter_mu[g * 64 + d0];
                    *(float4*)&out_ac[(size_t)row * 640 + 512 + d0] =
                        *(const float4*)&g_inter_sample[g * 64 + d0];
                } else {
                    float4 st;
                    st.x = softplusf(v.x - 5.f);
                    st.y = softplusf(v.y - 5.f);
                    st.z = softplusf(v.z - 5.f);
                    st.w = softplusf(v.w - 5.f);
                    float4 mu4 = *(const float4*)&MUb[l * 64 + d0];
                    float4 ep  = *(const float4*)&eps_intra[(size_t)row * 64 + d0];
                    float4 samp;
                    samp.x = fmaf(st.x, ep.x, mu4.x);
                    samp.y = fmaf(st.y, ep.y, mu4.y);
                    samp.z = fmaf(st.z, ep.z, mu4.z);
                    samp.w = fmaf(st.w, ep.w, mu4.w);
                    *(float4*)&out_std[(size_t)row * 128 + d0] = st;
                    *(float4*)&out_std[(size_t)row * 128 + 64 + d0] =
                        *(const float4*)&g_inter_std[g * 64 + d0];
                    *(float4*)&out_ac[(size_t)row * 640 + 576 + d0] = samp;
                }
            }
        }
    }
}

// ---------------------------------------------------------------------------
extern "C" void kernel_launch(void* const* d_in, const int* in_sizes, int n_in,
                              void* d_out, int out_size)
{
    (void)in_sizes; (void)n_in; (void)out_size;
    const float* obs        = (const float*)d_in[0];
    const int*   sets       = (const int*)  d_in[1];
    const float* eps_intra  = (const float*)d_in[2];
    const float* eps_inter  = (const float*)d_in[3];
    const float* local_w    = (const float*)d_in[4];
    const float* local_b    = (const float*)d_in[5];
    const float* inter_emb_w= (const float*)d_in[6];
    const float* inter_emb_b= (const float*)d_in[7];
    const float* intra_emb_w= (const float*)d_in[8];
    const float* intra_emb_b= (const float*)d_in[9];
    const float* amu_in_w   = (const float*)d_in[10];
    const float* amu_in_b   = (const float*)d_in[11];
    const float* amu_out_w  = (const float*)d_in[12];
    const float* amu_out_b  = (const float*)d_in[13];
    const float* astd_in_w  = (const float*)d_in[14];
    const float* astd_in_b  = (const float*)d_in[15];
    const float* astd_out_w = (const float*)d_in[16];
    const float* astd_out_b = (const float*)d_in[17];
    const float* emu_in_w   = (const float*)d_in[18];
    const float* emu_in_b   = (const float*)d_in[19];
    const float* emu_out_w  = (const float*)d_in[20];
    const float* emu_out_b  = (const float*)d_in[21];
    const float* estd_in_w  = (const float*)d_in[22];
    const float* estd_in_b  = (const float*)d_in[23];
    const float* estd_out_w = (const float*)d_in[24];
    const float* estd_out_b = (const float*)d_in[25];
    const float* attset_w   = (const float*)d_in[26];
    const float* attset_b   = (const float*)d_in[27];

    float* out_ac  = (float*)d_out;
    float* out_mu  = out_ac + (size_t)NN * 640;
    float* out_std = out_mu + (size_t)NN * 128;

    const int k2_smem  = (64*196 + 64*65 + 64*65 + 64 + 64*64) * 4 + 64 * 4;
    const int k4b_smem = (2 * 1024 * 16 + 8 * 64 * 2 + 8 * 64 * 16) * 4;
    cudaFuncSetAttribute(k2_intra, cudaFuncAttributeMaxDynamicSharedMemorySize, k2_smem);
    cudaFuncSetAttribute(k4b_attn, cudaFuncAttributeMaxDynamicSharedMemorySize, k4b_smem);
    cudaFuncSetAttribute(k1_mma, cudaFuncAttributeMaxDynamicSharedMemorySize, K1_SMEM);
    cudaFuncSetAttribute(k2a_qkv_gemm, cudaFuncAttributeMaxDynamicSharedMemorySize, K2A_SMEM);

    // split inputs into bf16 hi/lo
    k0_split_A<<<(NN * OBSD / 4 + 255) / 256, 256>>>((const float4*)obs);
    k0_split_W<<<640, 256>>>(local_w, local_b, inter_emb_w, inter_emb_b,
                             intra_emb_w, intra_emb_b);
    k0_split_Wq<<<384, 64>>>(amu_in_w, amu_in_b, astd_in_w, astd_in_b);

    dim3 g1(512, 10);
    k1_mma<<<g1, 256, K1_SMEM>>>(out_ac);
    dim3 g2a(512, 6);
    k2a_qkv_gemm<<<g2a, 256, K2A_SMEM>>>();

    k3_pool<<<GG, 256>>>(sets, attset_w, attset_b);
    dim3 g4a(16, 2);
    k4a_qkv<<<g4a, 256>>>(emu_in_w, emu_in_b, estd_in_w, estd_in_b);
    dim3 g4b(16, 4, 2);
    k4b_attn<<<g4b, 512, k4b_smem>>>();
    k4c_proj<<<16, 256>>>(emu_out_w, emu_out_b, estd_out_w, estd_out_b, eps_inter);
    k2_intra<<<GG, 256, k2_smem>>>(sets,
                                   amu_out_w, amu_out_b, astd_out_w, astd_out_b,
                                   eps_intra, out_ac, out_mu, out_std);
}